// round 13
// baseline (speedup 1.0000x reference)
#include <cuda_runtime.h>
#include <cuda_bf16.h>
#include <math.h>

// ---------------- constants ----------------
static constexpr int  Dm   = 768;
static constexpr int  NHd  = 12;
static constexpr int  HD   = 64;
static constexpr int  Nt   = 197;
static constexpr int  Bb   = 8;
static constexpr long Tt   = (long)Bb * Nt;       // 1576
static constexpr int  HIDm = 3072;
static constexpr int  Em   = 8;
static constexpr int  NP   = 196;

// float arena offsets
static constexpr long OFF_H     = 0;
static constexpr long OFF_Y     = OFF_H    + Tt * Dm;
static constexpr long OFF_QKV   = OFF_Y    + Tt * Dm;
static constexpr long OFF_ATTN  = OFF_QKV  + Tt * 3 * Dm;
static constexpr long OFF_HID   = OFF_ATTN + Tt * Dm;
static constexpr long OFF_MOE   = OFF_HID  + (long)Em * Tt * HIDm;
static constexpr long OFF_CLS   = OFF_MOE  + Tt * 2 * Dm;
static constexpr long OFF_PATCH = OFF_CLS  + (long)Bb * Dm;
static constexpr long OFF_SCALE = OFF_PATCH + (long)Bb * NP * Dm;
static constexpr long FTOTAL    = OFF_SCALE + (long)Em * Tt;

__device__ float g_fbuf[FTOTAL];
__device__ int   g_ibuf[8 + 2 * Em * 1576];

// ---------------- generic tiled GEMM (128x128x8, 8x8 microtile) ----------------
struct GemmP {
    const float* A; const float* B; const float* bias; float* C;
    int lda, ldb, ldc;
    int M, N, K;
    long sAz, sBz, sbz, sCz;
    const int* cnt;                 // per-z M override (device)
    const int* arow;  long sArz;    // optional A row gather
    const int* crow;  long sCrz;    // optional C row scatter
    const float* rsc; long sRz;     // optional per-row scale (epi 3)
    int epi;                        // 0 store, 1 +=, 2 gelu-store, 3 scale-scatter
};

__global__ __launch_bounds__(256, 2)
void gemm128(GemmP p)
{
    __shared__ float As[8][132];
    __shared__ float Bs[8][128];

    int z  = blockIdx.z;
    int Mz = p.cnt ? p.cnt[z] : p.M;
    int m0 = blockIdx.y * 128;
    if (m0 >= Mz) return;
    int n0 = blockIdx.x * 128;

    const float* A = p.A + z * p.sAz;
    const float* B = p.B + z * p.sBz;
    const int* arow = p.arow ? (p.arow + z * p.sArz) : nullptr;

    int tid = threadIdx.x;
    int ra = tid >> 1,  ka = (tid & 1) << 2;
    int kb = tid >> 5,  nb = (tid & 31) << 2;

    int  rg = m0 + ra;
    bool av = rg < Mz;
    long arw = 0;
    if (av) arw = arow ? (long)arow[rg] : (long)rg;
    const float* Ap = A + arw * p.lda + ka;
    const float* Bp = B + (long)kb * p.ldb + n0 + nb;

    float4 zf = make_float4(0.f, 0.f, 0.f, 0.f);
    float4 af = av ? *(const float4*)Ap : zf;
    float4 bf = *(const float4*)Bp;

    float acc[8][8];
#pragma unroll
    for (int i = 0; i < 8; i++)
#pragma unroll
        for (int j = 0; j < 8; j++) acc[i][j] = 0.f;

    int ty = tid >> 4, tx = tid & 15;
    int nsteps = p.K >> 3;

    for (int s = 0; s < nsteps; ++s) {
        As[ka  ][ra] = af.x;
        As[ka+1][ra] = af.y;
        As[ka+2][ra] = af.z;
        As[ka+3][ra] = af.w;
        *(float4*)&Bs[kb][nb] = bf;
        __syncthreads();
        if (s + 1 < nsteps) {
            af = av ? *(const float4*)(Ap + (long)(s + 1) * 8) : zf;
            bf = *(const float4*)(Bp + (long)(s + 1) * 8 * p.ldb);
        }
#pragma unroll
        for (int kk = 0; kk < 8; ++kk) {
            float a[8], b[8];
            *(float4*)&a[0] = *(const float4*)&As[kk][ty * 8];
            *(float4*)&a[4] = *(const float4*)&As[kk][ty * 8 + 4];
            *(float4*)&b[0] = *(const float4*)&Bs[kk][tx * 8];
            *(float4*)&b[4] = *(const float4*)&Bs[kk][tx * 8 + 4];
#pragma unroll
            for (int i = 0; i < 8; i++)
#pragma unroll
                for (int j = 0; j < 8; j++)
                    acc[i][j] += a[i] * b[j];
        }
        __syncthreads();
    }

    float* C = p.C + z * p.sCz;
    const float* bias = p.bias ? (p.bias + z * p.sbz) : nullptr;
    const int*   crow = p.crow ? (p.crow + z * p.sCrz) : nullptr;
    const float* rsc  = p.rsc  ? (p.rsc  + z * p.sRz)  : nullptr;

#pragma unroll
    for (int i = 0; i < 8; ++i) {
        int r = m0 + ty * 8 + i;
        if (r >= Mz) break;
        long cr = crow ? (long)crow[r] : (long)r;
        float sc = rsc ? rsc[r] : 1.0f;
        float* cp = C + cr * p.ldc + n0 + tx * 8;
#pragma unroll
        for (int j = 0; j < 8; ++j) {
            float v = acc[i][j] + (bias ? bias[n0 + tx * 8 + j] : 0.0f);
            if (p.epi == 2) v = 0.5f * v * (1.0f + erff(v * 0.70710678118654752f));
            if (p.epi == 1) cp[j] += v;
            else            cp[j]  = v * sc;
        }
    }
}

// ---------------- patchify ----------------
__global__ void patchify_kernel(const float* __restrict__ x, float* __restrict__ P)
{
    int row = blockIdx.x;              // b*196 + pidx
    int b = row / NP, pidx = row % NP;
    int gy = pidx / 14, gx = pidx % 14;
    for (int k = threadIdx.x; k < Dm; k += 256) {
        int c = k >> 8, rem = k & 255, py = rem >> 4, px = rem & 15;
        P[(long)row * Dm + k] =
            x[((long)(b * 3 + c) * 224 + gy * 16 + py) * 224 + gx * 16 + px];
    }
}

// ---------------- assemble tokens (cls + pos) ----------------
__global__ void assemble_kernel(const float* __restrict__ tok, const float* __restrict__ cls,
                                const float* __restrict__ pos, float* __restrict__ h)
{
    int t = blockIdx.x;
    int b = t / Nt, n = t % Nt;
    for (int c = threadIdx.x; c < Dm; c += 256) {
        float v = (n == 0) ? cls[c] : tok[(long)(b * NP + n - 1) * Dm + c];
        h[(long)t * Dm + c] = v + pos[(long)n * Dm + c];
    }
}

// ---------------- layernorm (768 wide, 256 threads) ----------------
__global__ void ln_kernel(const float* __restrict__ x, const float* __restrict__ g,
                          const float* __restrict__ bb, float* __restrict__ y, int row_mul)
{
    int ro = blockIdx.x;
    const float* xr = x + (long)ro * row_mul * Dm;
    float* yr = y + (long)ro * Dm;
    int tid = threadIdx.x;
    float v0 = xr[tid], v1 = xr[tid + 256], v2 = xr[tid + 512];
    float s  = v0 + v1 + v2;
    float ss = v0 * v0 + v1 * v1 + v2 * v2;
#pragma unroll
    for (int off = 16; off; off >>= 1) {
        s  += __shfl_xor_sync(0xffffffffu, s,  off);
        ss += __shfl_xor_sync(0xffffffffu, ss, off);
    }
    __shared__ float sh[16];
    __shared__ float stat[2];
    int w = tid >> 5, l = tid & 31;
    if (l == 0) { sh[w] = s; sh[8 + w] = ss; }
    __syncthreads();
    if (tid == 0) {
        float S = 0.f, SS = 0.f;
        for (int i = 0; i < 8; i++) { S += sh[i]; SS += sh[8 + i]; }
        float m = S * (1.0f / 768.0f);
        float var = SS * (1.0f / 768.0f) - m * m;
        stat[0] = m;
        stat[1] = rsqrtf(var + 1e-5f);
    }
    __syncthreads();
    float m = stat[0], r = stat[1];
    yr[tid]       = (v0 - m) * r * g[tid]       + bb[tid];
    yr[tid + 256] = (v1 - m) * r * g[tid + 256] + bb[tid + 256];
    yr[tid + 512] = (v2 - m) * r * g[tid + 512] + bb[tid + 512];
}

// ---------------- attention (per (head, batch) block) ----------------
static constexpr int ATT_SMEM = (2 * Nt * HD + 8 * 208) * 4;   // ~107.5 KB

__global__ void attn_kernel(const float* __restrict__ qkv, float* __restrict__ out)
{
    extern __shared__ float sm[];
    float* Ks = sm;
    float* Vs = sm + Nt * HD;
    float* Ps = sm + 2 * Nt * HD;

    int h = blockIdx.x, b = blockIdx.y;
    int tid = threadIdx.x;

    for (int idx = tid; idx < Nt * 16; idx += 256) {
        int n = idx >> 4, d4 = (idx & 15) << 2;
        const float* base = qkv + (long)(b * Nt + n) * (3 * Dm) + h * HD + d4;
        *(float4*)&Ks[n * HD + d4] = *(const float4*)(base + Dm);
        *(float4*)&Vs[n * HD + d4] = *(const float4*)(base + 2 * Dm);
    }
    __syncthreads();

    int warp = tid >> 5, lane = tid & 31;
    float* pr = Ps + warp * 208;

    for (int r = warp; r < Nt; r += 8) {
        const float* qg = qkv + (long)(b * Nt + r) * (3 * Dm) + h * HD;
        float q[HD];
#pragma unroll
        for (int d4 = 0; d4 < HD; d4 += 4)
            *(float4*)&q[d4] = *(const float4*)(qg + d4);

        float mx = -1e30f;
        for (int j = lane; j < Nt; j += 32) {
            const float* kr = Ks + j * HD;
            float sv = 0.f;
#pragma unroll
            for (int d4 = 0; d4 < HD; d4 += 4) {
                float4 k4 = *(const float4*)(kr + d4);
                sv += q[d4] * k4.x + q[d4 + 1] * k4.y + q[d4 + 2] * k4.z + q[d4 + 3] * k4.w;
            }
            sv *= 0.125f;
            pr[j] = sv;
            mx = fmaxf(mx, sv);
        }
#pragma unroll
        for (int off = 16; off; off >>= 1)
            mx = fmaxf(mx, __shfl_xor_sync(0xffffffffu, mx, off));

        __syncwarp();
        float sum = 0.f;
        for (int j = lane; j < Nt; j += 32) {
            float pv = expf(pr[j] - mx);
            pr[j] = pv;
            sum += pv;
        }
#pragma unroll
        for (int off = 16; off; off >>= 1)
            sum += __shfl_xor_sync(0xffffffffu, sum, off);
        __syncwarp();

        float inv = 1.0f / sum;
        float o0 = 0.f, o1 = 0.f;
        for (int j = 0; j < Nt; j++) {
            float pv = pr[j];
            o0 += pv * Vs[j * HD + lane];
            o1 += pv * Vs[j * HD + lane + 32];
        }
        float* op = out + (long)(b * Nt + r) * Dm + h * HD;
        op[lane]      = o0 * inv;
        op[lane + 32] = o1 * inv;
        __syncwarp();
    }
}

// ---------------- MoE gate + routing ----------------
__global__ void zero_cnt_kernel(int* c) { if (threadIdx.x < 8) c[threadIdx.x] = 0; }

__global__ void gate_kernel(const float* __restrict__ y, const float* __restrict__ wg,
                            int* cnt, int* list, int* crow, float* scale)
{
    int warp = threadIdx.x >> 5, lane = threadIdx.x & 31;
    int t = blockIdx.x * 8 + warp;
    if (t >= (int)Tt) return;
    float lg[8] = {0, 0, 0, 0, 0, 0, 0, 0};
    const float* yr = y + (long)t * Dm;
    for (int d = lane; d < Dm; d += 32) {
        float xv = yr[d];
        const float* w = wg + d * Em;
#pragma unroll
        for (int e = 0; e < 8; e++) lg[e] += xv * w[e];
    }
#pragma unroll
    for (int e = 0; e < 8; e++)
#pragma unroll
        for (int off = 16; off; off >>= 1)
            lg[e] += __shfl_xor_sync(0xffffffffu, lg[e], off);
    if (lane == 0) {
        int e0 = 0; float v0 = lg[0];
        for (int e = 1; e < 8; e++) if (lg[e] > v0) { v0 = lg[e]; e0 = e; }
        int e1 = (e0 == 0) ? 1 : 0; float v1 = lg[e1];
        for (int e = 0; e < 8; e++)
            if (e != e0 && lg[e] > v1) { v1 = lg[e]; e1 = e; }
        float p0 = 1.0f / (1.0f + expf(v1 - v0));
        float p1 = 1.0f - p0;
        int pos = atomicAdd(&cnt[e0], 1);
        list[e0 * 1576 + pos] = t; crow[e0 * 1576 + pos] = t * 2;     scale[e0 * 1576 + pos] = p0;
        pos = atomicAdd(&cnt[e1], 1);
        list[e1 * 1576 + pos] = t; crow[e1 * 1576 + pos] = t * 2 + 1; scale[e1 * 1576 + pos] = p1;
    }
}

__global__ void moe_combine_kernel(const float* __restrict__ mo, float* __restrict__ h)
{
    long t = blockIdx.x;
    for (int c = threadIdx.x; c < Dm; c += 256)
        h[t * Dm + c] += mo[t * 2 * Dm + c] + mo[t * 2 * Dm + Dm + c];
}

// ---------------- head ----------------
__global__ void head_kernel(const float* __restrict__ cls, const float* __restrict__ w,
                            const float* __restrict__ bh, float* __restrict__ out)
{
    int c = blockIdx.x * 256 + threadIdx.x;
    int b = blockIdx.y;
    if (c >= 1000) return;
    const float* cr = cls + (long)b * Dm;
    float s0 = 0.f, s1 = 0.f, s2 = 0.f, s3 = 0.f;
    for (int d = 0; d < Dm; d += 4) {
        s0 += cr[d]     * w[(long)d * 1000 + c];
        s1 += cr[d + 1] * w[(long)(d + 1) * 1000 + c];
        s2 += cr[d + 2] * w[(long)(d + 2) * 1000 + c];
        s3 += cr[d + 3] * w[(long)(d + 3) * 1000 + c];
    }
    out[(long)b * 1000 + c] = (s0 + s1) + (s2 + s3) + bh[c];
}

// ---------------- host-side launcher ----------------
static inline void launch_gemm(const float* A, long sAz, int lda,
                               const float* B, long sBz, int ldb,
                               const float* bias, long sbz,
                               float* C, long sCz, int ldc,
                               int M, const int* cnt, int N, int K,
                               const int* arow, long sArz,
                               const int* crow, long sCrz,
                               const float* rsc, long sRz,
                               int epi, int Z)
{
    GemmP p;
    p.A = A; p.B = B; p.bias = bias; p.C = C;
    p.lda = lda; p.ldb = ldb; p.ldc = ldc;
    p.M = M; p.N = N; p.K = K;
    p.sAz = sAz; p.sBz = sBz; p.sbz = sbz; p.sCz = sCz;
    p.cnt = cnt;
    p.arow = arow; p.sArz = sArz;
    p.crow = crow; p.sCrz = sCrz;
    p.rsc = rsc;  p.sRz  = sRz;
    p.epi = epi;
    dim3 grid(N / 128, (M + 127) / 128, Z);
    gemm128<<<grid, 256>>>(p);
}

extern "C" void kernel_launch(void* const* d_in, const int* in_sizes, int n_in,
                              void* d_out, int out_size)
{
    const float* X      = (const float*)d_in[0];
    const float* Wpatch = (const float*)d_in[1];
    const float* Bpatch = (const float*)d_in[2];
    const float* Cls    = (const float*)d_in[3];
    const float* Pos    = (const float*)d_in[4];
    const float* Ln1g   = (const float*)d_in[5];
    const float* Ln1b   = (const float*)d_in[6];
    const float* Wqkv   = (const float*)d_in[7];
    const float* Wproj  = (const float*)d_in[8];
    const float* Bproj  = (const float*)d_in[9];
    const float* Ln2g   = (const float*)d_in[10];
    const float* Ln2b   = (const float*)d_in[11];
    const float* Wfc1   = (const float*)d_in[12];
    const float* Bfc1   = (const float*)d_in[13];
    const float* Wfc2   = (const float*)d_in[14];
    const float* Bfc2   = (const float*)d_in[15];
    const float* Wgate  = (const float*)d_in[16];
    const float* We1    = (const float*)d_in[17];
    const float* Be1    = (const float*)d_in[18];
    const float* We2    = (const float*)d_in[19];
    const float* Be2    = (const float*)d_in[20];
    const float* Lnfg   = (const float*)d_in[21];
    const float* Lnfb   = (const float*)d_in[22];
    const float* Whead  = (const float*)d_in[23];
    const float* Bhead  = (const float*)d_in[24];
    float* OUT = (float*)d_out;

    float* FB = nullptr; int* IB = nullptr;
    cudaGetSymbolAddress((void**)&FB, g_fbuf);
    cudaGetSymbolAddress((void**)&IB, g_ibuf);

    float* H    = FB + OFF_H;
    float* Y    = FB + OFF_Y;
    float* QKV  = FB + OFF_QKV;
    float* AT   = FB + OFF_ATTN;
    float* HID  = FB + OFF_HID;
    float* MO   = FB + OFF_MOE;
    float* CLSB = FB + OFF_CLS;
    float* PB   = FB + OFF_PATCH;
    float* SCB  = FB + OFF_SCALE;
    int* CNT  = IB;
    int* LIST = IB + 8;
    int* CROW = IB + 8 + 8 * 1576;

    cudaFuncSetAttribute(attn_kernel, cudaFuncAttributeMaxDynamicSharedMemorySize, ATT_SMEM);

    const int T = (int)Tt;

    // patch embed
    patchify_kernel<<<Bb * NP, 256>>>(X, PB);
    launch_gemm(PB, 0, Dm, Wpatch, 0, Dm, Bpatch, 0,
                AT, 0, Dm, Bb * NP, nullptr, Dm, Dm,
                nullptr, 0, nullptr, 0, nullptr, 0, /*epi*/0, 1);
    assemble_kernel<<<T, 256>>>(AT, Cls, Pos, H);

    for (int i = 0; i < 4; i++) {
        // attention block
        ln_kernel<<<T, 256>>>(H, Ln1g + i * Dm, Ln1b + i * Dm, Y, 1);
        launch_gemm(Y, 0, Dm, Wqkv + (long)i * Dm * 3 * Dm, 0, 3 * Dm, nullptr, 0,
                    QKV, 0, 3 * Dm, T, nullptr, 3 * Dm, Dm,
                    nullptr, 0, nullptr, 0, nullptr, 0, 0, 1);
        attn_kernel<<<dim3(NHd, Bb), 256, ATT_SMEM>>>(QKV, AT);
        launch_gemm(AT, 0, Dm, Wproj + (long)i * Dm * Dm, 0, Dm, Bproj + (long)i * Dm, 0,
                    H, 0, Dm, T, nullptr, Dm, Dm,
                    nullptr, 0, nullptr, 0, nullptr, 0, /*+=*/1, 1);

        // MLP block
        ln_kernel<<<T, 256>>>(H, Ln2g + i * Dm, Ln2b + i * Dm, Y, 1);
        int j = i >> 1;
        if ((i & 1) == 0) {
            launch_gemm(Y, 0, Dm, Wfc1 + (long)j * Dm * HIDm, 0, HIDm,
                        Bfc1 + (long)j * HIDm, 0,
                        HID, 0, HIDm, T, nullptr, HIDm, Dm,
                        nullptr, 0, nullptr, 0, nullptr, 0, /*gelu*/2, 1);
            launch_gemm(HID, 0, HIDm, Wfc2 + (long)j * HIDm * Dm, 0, Dm,
                        Bfc2 + (long)j * Dm, 0,
                        H, 0, Dm, T, nullptr, Dm, HIDm,
                        nullptr, 0, nullptr, 0, nullptr, 0, /*+=*/1, 1);
        } else {
            zero_cnt_kernel<<<1, 8>>>(CNT);
            gate_kernel<<<(T + 7) / 8, 256>>>(Y, Wgate + (long)j * Dm * Em,
                                              CNT, LIST, CROW, SCB);
            // expert fc1 (gathered rows of Y) -> gelu -> HID[e]
            launch_gemm(Y, 0, Dm,
                        We1 + (long)j * Em * Dm * HIDm, (long)Dm * HIDm, HIDm,
                        Be1 + (long)j * Em * HIDm, HIDm,
                        HID, (long)T * HIDm, HIDm,
                        T, CNT, HIDm, Dm,
                        LIST, 1576, nullptr, 0, nullptr, 0, /*gelu*/2, Em);
            // expert fc2 -> scaled scatter into (token, slot) rows of MO
            launch_gemm(HID, (long)T * HIDm, HIDm,
                        We2 + (long)j * Em * HIDm * Dm, (long)HIDm * Dm, Dm,
                        Be2 + (long)j * Em * Dm, Dm,
                        MO, 0, Dm,
                        T, CNT, Dm, HIDm,
                        nullptr, 0, CROW, 1576, SCB, 1576, /*scatter*/3, Em);
            moe_combine_kernel<<<T, 256>>>(MO, H);
        }
    }

    // final LN on cls rows + head
    ln_kernel<<<Bb, 256>>>(H, Lnfg, Lnfb, CLSB, Nt);
    head_kernel<<<dim3(4, Bb), 256>>>(CLSB, Whead, Bhead, OUT);
}

// round 14
// speedup vs baseline: 2.0596x; 2.0596x over previous
#include <cuda_runtime.h>
#include <cuda_bf16.h>
#include <math.h>

// ---------------- constants ----------------
static constexpr int  Dm   = 768;
static constexpr int  NHd  = 12;
static constexpr int  HD   = 64;
static constexpr int  Nt   = 197;
static constexpr int  Bb   = 8;
static constexpr long Tt   = (long)Bb * Nt;       // 1576
static constexpr int  HIDm = 3072;
static constexpr int  Em   = 8;
static constexpr int  NP   = 196;

// float arena offsets
static constexpr long OFF_H     = 0;
static constexpr long OFF_Y     = OFF_H    + Tt * Dm;
static constexpr long OFF_QKV   = OFF_Y    + Tt * Dm;
static constexpr long OFF_ATTN  = OFF_QKV  + Tt * 3 * Dm;
static constexpr long OFF_HID   = OFF_ATTN + Tt * Dm;
static constexpr long OFF_MOE   = OFF_HID  + (long)Em * Tt * HIDm;
static constexpr long OFF_CLS   = OFF_MOE  + Tt * 2 * Dm;
static constexpr long OFF_PATCH = OFF_CLS  + (long)Bb * Dm;
static constexpr long OFF_SCALE = OFF_PATCH + (long)Bb * NP * Dm;
static constexpr long FTOTAL    = OFF_SCALE + (long)Em * Tt;

__device__ float g_fbuf[FTOTAL];
__device__ int   g_ibuf[8 + 2 * Em * 1576];

// ---------------- TF32 helpers ----------------
__device__ __forceinline__ unsigned f2tf(float f) {
    unsigned r;
    asm("cvt.rna.tf32.f32 %0, %1;" : "=r"(r) : "f"(f));
    return r;
}

#define MMA_TF32(d, aa, bb)                                                    \
    asm volatile(                                                              \
        "mma.sync.aligned.m16n8k8.row.col.f32.tf32.tf32.f32 "                  \
        "{%0,%1,%2,%3}, {%4,%5,%6,%7}, {%8,%9}, {%0,%1,%2,%3};"                \
        : "+f"(d[0]), "+f"(d[1]), "+f"(d[2]), "+f"(d[3])                       \
        : "r"(aa[0]), "r"(aa[1]), "r"(aa[2]), "r"(aa[3]),                      \
          "r"(bb[0]), "r"(bb[1]))

// ---------------- grouped GEMM params ----------------
struct GemmP {
    const float* A; const float* B; const float* bias; float* C;
    int lda, ldb, ldc;
    int M, N, K;
    long sAz, sBz, sbz, sCz;
    const int* cnt;                 // per-z M override (device)
    const int* arow;  long sArz;    // optional A row gather
    const int* crow;  long sCrz;    // optional C row scatter
    const float* rsc; long sRz;     // optional per-row scale (epi 3)
    int epi;                        // 0 store, 1 +=, 2 gelu-store, 3 scale-scatter
};

// TF32 tensor-core GEMM: block 128x128, warp 32x64, K-stage 16.
__global__ __launch_bounds__(256)
void gemm_tf32(GemmP p)
{
    __shared__ unsigned As[16][136];   // [k][m], pad 136 -> conflict-free frag loads
    __shared__ unsigned Bs[16][136];   // [k][n]

    int z  = blockIdx.z;
    int Mz = p.cnt ? p.cnt[z] : p.M;
    int m0 = blockIdx.y * 128;
    if (m0 >= Mz) return;
    int n0 = blockIdx.x * 128;

    const float* A = p.A + z * p.sAz;
    const float* B = p.B + z * p.sBz;
    const int* arow = p.arow ? (p.arow + z * p.sArz) : nullptr;

    int tid = threadIdx.x;

    // A loader: row ma = tid>>1, k-offset ka = (tid&1)*8 (two float4 along k)
    int ma = tid >> 1;
    int ka = (tid & 1) << 3;
    int rg = m0 + ma;
    bool av = rg < Mz;
    long arw = av ? (arow ? (long)arow[rg] : (long)rg) : 0;
    const float* Ap = A + arw * p.lda + ka;

    // B loader: kb = tid>>4 (0..15), n = (tid&15)*4 and +64 (two float4 along n)
    int kb  = tid >> 4;
    int nbq = (tid & 15) << 2;
    const float* Bp = B + (long)kb * p.ldb + n0 + nbq;

    float4 zf = make_float4(0.f, 0.f, 0.f, 0.f);
    float4 a0 = zf, a1 = zf;
    if (av) { a0 = *(const float4*)Ap; a1 = *(const float4*)(Ap + 4); }
    float4 b0 = *(const float4*)Bp;
    float4 b1 = *(const float4*)(Bp + 64);

    float acc[2][8][4];
#pragma unroll
    for (int i = 0; i < 2; i++)
#pragma unroll
        for (int j = 0; j < 8; j++)
#pragma unroll
            for (int q = 0; q < 4; q++) acc[i][j][q] = 0.f;

    int warp = tid >> 5, lane = tid & 31;
    int wm = (warp & 3) << 5;        // 0,32,64,96
    int wn = (warp >> 2) << 6;       // 0,64
    int qr = lane >> 2;              // 0..7
    int qk = lane & 3;               // 0..3

    int nsteps = p.K >> 4;
    for (int s = 0; s < nsteps; ++s) {
        // stage registers -> smem (converted to tf32)
        As[ka + 0][ma] = f2tf(a0.x);
        As[ka + 1][ma] = f2tf(a0.y);
        As[ka + 2][ma] = f2tf(a0.z);
        As[ka + 3][ma] = f2tf(a0.w);
        As[ka + 4][ma] = f2tf(a1.x);
        As[ka + 5][ma] = f2tf(a1.y);
        As[ka + 6][ma] = f2tf(a1.z);
        As[ka + 7][ma] = f2tf(a1.w);
        *(uint4*)&Bs[kb][nbq]      = make_uint4(f2tf(b0.x), f2tf(b0.y), f2tf(b0.z), f2tf(b0.w));
        *(uint4*)&Bs[kb][nbq + 64] = make_uint4(f2tf(b1.x), f2tf(b1.y), f2tf(b1.z), f2tf(b1.w));
        __syncthreads();

        if (s + 1 < nsteps) {
            if (av) {
                a0 = *(const float4*)(Ap + (long)(s + 1) * 16);
                a1 = *(const float4*)(Ap + (long)(s + 1) * 16 + 4);
            }
            b0 = *(const float4*)(Bp + (long)(s + 1) * 16 * p.ldb);
            b1 = *(const float4*)(Bp + (long)(s + 1) * 16 * p.ldb + 64);
        }

#pragma unroll
        for (int kk = 0; kk < 16; kk += 8) {
            unsigned af[2][4];
#pragma unroll
            for (int mt = 0; mt < 2; mt++) {
                int mr = wm + mt * 16 + qr;
                af[mt][0] = As[kk + qk    ][mr];
                af[mt][1] = As[kk + qk    ][mr + 8];
                af[mt][2] = As[kk + qk + 4][mr];
                af[mt][3] = As[kk + qk + 4][mr + 8];
            }
            unsigned bfg[8][2];
#pragma unroll
            for (int nt = 0; nt < 8; nt++) {
                int nc = wn + nt * 8 + qr;
                bfg[nt][0] = Bs[kk + qk    ][nc];
                bfg[nt][1] = Bs[kk + qk + 4][nc];
            }
#pragma unroll
            for (int mt = 0; mt < 2; mt++)
#pragma unroll
                for (int nt = 0; nt < 8; nt++)
                    MMA_TF32(acc[mt][nt], af[mt], bfg[nt]);
        }
        __syncthreads();
    }

    // ---------------- epilogue ----------------
    float* C = p.C + z * p.sCz;
    const float* bias = p.bias ? (p.bias + z * p.sbz) : nullptr;
    const int*   crow = p.crow ? (p.crow + z * p.sCrz) : nullptr;
    const float* rsc  = p.rsc  ? (p.rsc  + z * p.sRz)  : nullptr;

#pragma unroll
    for (int mt = 0; mt < 2; mt++) {
#pragma unroll
        for (int half = 0; half < 2; half++) {
            int r = m0 + wm + mt * 16 + qr + half * 8;
            if (r >= Mz) continue;
            long cr = crow ? (long)crow[r] : (long)r;
            float sc = rsc ? rsc[r] : 1.0f;
            float* crp = C + cr * p.ldc;
#pragma unroll
            for (int nt = 0; nt < 8; nt++) {
                int c = n0 + wn + nt * 8 + qk * 2;
                float v0 = acc[mt][nt][half * 2 + 0];
                float v1 = acc[mt][nt][half * 2 + 1];
                if (bias) { v0 += bias[c]; v1 += bias[c + 1]; }
                if (p.epi == 2) {
                    v0 = 0.5f * v0 * (1.0f + erff(v0 * 0.70710678118654752f));
                    v1 = 0.5f * v1 * (1.0f + erff(v1 * 0.70710678118654752f));
                }
                float* cp = crp + c;
                if (p.epi == 1) {
                    float2 old = *(float2*)cp;
                    *(float2*)cp = make_float2(old.x + v0, old.y + v1);
                } else {
                    *(float2*)cp = make_float2(v0 * sc, v1 * sc);
                }
            }
        }
    }
}

// ---------------- patchify ----------------
__global__ void patchify_kernel(const float* __restrict__ x, float* __restrict__ P)
{
    int row = blockIdx.x;              // b*196 + pidx
    int b = row / NP, pidx = row % NP;
    int gy = pidx / 14, gx = pidx % 14;
    for (int k = threadIdx.x; k < Dm; k += 256) {
        int c = k >> 8, rem = k & 255, py = rem >> 4, px = rem & 15;
        P[(long)row * Dm + k] =
            x[((long)(b * 3 + c) * 224 + gy * 16 + py) * 224 + gx * 16 + px];
    }
}

// ---------------- assemble tokens (cls + pos) ----------------
__global__ void assemble_kernel(const float* __restrict__ tok, const float* __restrict__ cls,
                                const float* __restrict__ pos, float* __restrict__ h)
{
    int t = blockIdx.x;
    int b = t / Nt, n = t % Nt;
    for (int c = threadIdx.x; c < Dm; c += 256) {
        float v = (n == 0) ? cls[c] : tok[(long)(b * NP + n - 1) * Dm + c];
        h[(long)t * Dm + c] = v + pos[(long)n * Dm + c];
    }
}

// ---------------- layernorm (768 wide, 256 threads) ----------------
__global__ void ln_kernel(const float* __restrict__ x, const float* __restrict__ g,
                          const float* __restrict__ bb, float* __restrict__ y, int row_mul)
{
    int ro = blockIdx.x;
    const float* xr = x + (long)ro * row_mul * Dm;
    float* yr = y + (long)ro * Dm;
    int tid = threadIdx.x;
    float v0 = xr[tid], v1 = xr[tid + 256], v2 = xr[tid + 512];
    float s  = v0 + v1 + v2;
    float ss = v0 * v0 + v1 * v1 + v2 * v2;
#pragma unroll
    for (int off = 16; off; off >>= 1) {
        s  += __shfl_xor_sync(0xffffffffu, s,  off);
        ss += __shfl_xor_sync(0xffffffffu, ss, off);
    }
    __shared__ float sh[16];
    __shared__ float stat[2];
    int w = tid >> 5, l = tid & 31;
    if (l == 0) { sh[w] = s; sh[8 + w] = ss; }
    __syncthreads();
    if (tid == 0) {
        float S = 0.f, SS = 0.f;
        for (int i = 0; i < 8; i++) { S += sh[i]; SS += sh[8 + i]; }
        float m = S * (1.0f / 768.0f);
        float var = SS * (1.0f / 768.0f) - m * m;
        stat[0] = m;
        stat[1] = rsqrtf(var + 1e-5f);
    }
    __syncthreads();
    float m = stat[0], r = stat[1];
    yr[tid]       = (v0 - m) * r * g[tid]       + bb[tid];
    yr[tid + 256] = (v1 - m) * r * g[tid + 256] + bb[tid + 256];
    yr[tid + 512] = (v2 - m) * r * g[tid + 512] + bb[tid + 512];
}

// ---------------- attention (per (head, batch) block) ----------------
static constexpr int ATT_SMEM = (2 * Nt * HD + 8 * 208) * 4;   // ~107.5 KB

__global__ void attn_kernel(const float* __restrict__ qkv, float* __restrict__ out)
{
    extern __shared__ float sm[];
    float* Ks = sm;
    float* Vs = sm + Nt * HD;
    float* Ps = sm + 2 * Nt * HD;

    int h = blockIdx.x, b = blockIdx.y;
    int tid = threadIdx.x;

    for (int idx = tid; idx < Nt * 16; idx += 256) {
        int n = idx >> 4, d4 = (idx & 15) << 2;
        const float* base = qkv + (long)(b * Nt + n) * (3 * Dm) + h * HD + d4;
        *(float4*)&Ks[n * HD + d4] = *(const float4*)(base + Dm);
        *(float4*)&Vs[n * HD + d4] = *(const float4*)(base + 2 * Dm);
    }
    __syncthreads();

    int warp = tid >> 5, lane = tid & 31;
    float* pr = Ps + warp * 208;

    for (int r = warp; r < Nt; r += 8) {
        const float* qg = qkv + (long)(b * Nt + r) * (3 * Dm) + h * HD;
        float q[HD];
#pragma unroll
        for (int d4 = 0; d4 < HD; d4 += 4)
            *(float4*)&q[d4] = *(const float4*)(qg + d4);

        float mx = -1e30f;
        for (int j = lane; j < Nt; j += 32) {
            const float* kr = Ks + j * HD;
            float sv = 0.f;
#pragma unroll
            for (int d4 = 0; d4 < HD; d4 += 4) {
                float4 k4 = *(const float4*)(kr + d4);
                sv += q[d4] * k4.x + q[d4 + 1] * k4.y + q[d4 + 2] * k4.z + q[d4 + 3] * k4.w;
            }
            sv *= 0.125f;
            pr[j] = sv;
            mx = fmaxf(mx, sv);
        }
#pragma unroll
        for (int off = 16; off; off >>= 1)
            mx = fmaxf(mx, __shfl_xor_sync(0xffffffffu, mx, off));

        __syncwarp();
        float sum = 0.f;
        for (int j = lane; j < Nt; j += 32) {
            float pv = expf(pr[j] - mx);
            pr[j] = pv;
            sum += pv;
        }
#pragma unroll
        for (int off = 16; off; off >>= 1)
            sum += __shfl_xor_sync(0xffffffffu, sum, off);
        __syncwarp();

        float inv = 1.0f / sum;
        float o0 = 0.f, o1 = 0.f;
        for (int j = 0; j < Nt; j++) {
            float pv = pr[j];
            o0 += pv * Vs[j * HD + lane];
            o1 += pv * Vs[j * HD + lane + 32];
        }
        float* op = out + (long)(b * Nt + r) * Dm + h * HD;
        op[lane]      = o0 * inv;
        op[lane + 32] = o1 * inv;
        __syncwarp();
    }
}

// ---------------- MoE gate + routing ----------------
__global__ void zero_cnt_kernel(int* c) { if (threadIdx.x < 8) c[threadIdx.x] = 0; }

__global__ void gate_kernel(const float* __restrict__ y, const float* __restrict__ wg,
                            int* cnt, int* list, int* crow, float* scale)
{
    int warp = threadIdx.x >> 5, lane = threadIdx.x & 31;
    int t = blockIdx.x * 8 + warp;
    if (t >= (int)Tt) return;
    float lg[8] = {0, 0, 0, 0, 0, 0, 0, 0};
    const float* yr = y + (long)t * Dm;
    for (int d = lane; d < Dm; d += 32) {
        float xv = yr[d];
        const float* w = wg + d * Em;
#pragma unroll
        for (int e = 0; e < 8; e++) lg[e] += xv * w[e];
    }
#pragma unroll
    for (int e = 0; e < 8; e++)
#pragma unroll
        for (int off = 16; off; off >>= 1)
            lg[e] += __shfl_xor_sync(0xffffffffu, lg[e], off);
    if (lane == 0) {
        int e0 = 0; float v0 = lg[0];
        for (int e = 1; e < 8; e++) if (lg[e] > v0) { v0 = lg[e]; e0 = e; }
        int e1 = (e0 == 0) ? 1 : 0; float v1 = lg[e1];
        for (int e = 0; e < 8; e++)
            if (e != e0 && lg[e] > v1) { v1 = lg[e]; e1 = e; }
        float p0 = 1.0f / (1.0f + expf(v1 - v0));
        float p1 = 1.0f - p0;
        int pos = atomicAdd(&cnt[e0], 1);
        list[e0 * 1576 + pos] = t; crow[e0 * 1576 + pos] = t * 2;     scale[e0 * 1576 + pos] = p0;
        pos = atomicAdd(&cnt[e1], 1);
        list[e1 * 1576 + pos] = t; crow[e1 * 1576 + pos] = t * 2 + 1; scale[e1 * 1576 + pos] = p1;
    }
}

__global__ void moe_combine_kernel(const float* __restrict__ mo, float* __restrict__ h)
{
    long t = blockIdx.x;
    for (int c = threadIdx.x; c < Dm; c += 256)
        h[t * Dm + c] += mo[t * 2 * Dm + c] + mo[t * 2 * Dm + Dm + c];
}

// ---------------- head ----------------
__global__ void head_kernel(const float* __restrict__ cls, const float* __restrict__ w,
                            const float* __restrict__ bh, float* __restrict__ out)
{
    int c = blockIdx.x * 256 + threadIdx.x;
    int b = blockIdx.y;
    if (c >= 1000) return;
    const float* cr = cls + (long)b * Dm;
    float s0 = 0.f, s1 = 0.f, s2 = 0.f, s3 = 0.f;
    for (int d = 0; d < Dm; d += 4) {
        s0 += cr[d]     * w[(long)d * 1000 + c];
        s1 += cr[d + 1] * w[(long)(d + 1) * 1000 + c];
        s2 += cr[d + 2] * w[(long)(d + 2) * 1000 + c];
        s3 += cr[d + 3] * w[(long)(d + 3) * 1000 + c];
    }
    out[(long)b * 1000 + c] = (s0 + s1) + (s2 + s3) + bh[c];
}

// ---------------- host-side launcher ----------------
static inline void launch_gemm(const float* A, long sAz, int lda,
                               const float* B, long sBz, int ldb,
                               const float* bias, long sbz,
                               float* C, long sCz, int ldc,
                               int M, const int* cnt, int N, int K,
                               const int* arow, long sArz,
                               const int* crow, long sCrz,
                               const float* rsc, long sRz,
                               int epi, int Z)
{
    GemmP p;
    p.A = A; p.B = B; p.bias = bias; p.C = C;
    p.lda = lda; p.ldb = ldb; p.ldc = ldc;
    p.M = M; p.N = N; p.K = K;
    p.sAz = sAz; p.sBz = sBz; p.sbz = sbz; p.sCz = sCz;
    p.cnt = cnt;
    p.arow = arow; p.sArz = sArz;
    p.crow = crow; p.sCrz = sCrz;
    p.rsc = rsc;  p.sRz  = sRz;
    p.epi = epi;
    dim3 grid(N / 128, (M + 127) / 128, Z);
    gemm_tf32<<<grid, 256>>>(p);
}

extern "C" void kernel_launch(void* const* d_in, const int* in_sizes, int n_in,
                              void* d_out, int out_size)
{
    const float* X      = (const float*)d_in[0];
    const float* Wpatch = (const float*)d_in[1];
    const float* Bpatch = (const float*)d_in[2];
    const float* Cls    = (const float*)d_in[3];
    const float* Pos    = (const float*)d_in[4];
    const float* Ln1g   = (const float*)d_in[5];
    const float* Ln1b   = (const float*)d_in[6];
    const float* Wqkv   = (const float*)d_in[7];
    const float* Wproj  = (const float*)d_in[8];
    const float* Bproj  = (const float*)d_in[9];
    const float* Ln2g   = (const float*)d_in[10];
    const float* Ln2b   = (const float*)d_in[11];
    const float* Wfc1   = (const float*)d_in[12];
    const float* Bfc1   = (const float*)d_in[13];
    const float* Wfc2   = (const float*)d_in[14];
    const float* Bfc2   = (const float*)d_in[15];
    const float* Wgate  = (const float*)d_in[16];
    const float* We1    = (const float*)d_in[17];
    const float* Be1    = (const float*)d_in[18];
    const float* We2    = (const float*)d_in[19];
    const float* Be2    = (const float*)d_in[20];
    const float* Lnfg   = (const float*)d_in[21];
    const float* Lnfb   = (const float*)d_in[22];
    const float* Whead  = (const float*)d_in[23];
    const float* Bhead  = (const float*)d_in[24];
    float* OUT = (float*)d_out;

    float* FB = nullptr; int* IB = nullptr;
    cudaGetSymbolAddress((void**)&FB, g_fbuf);
    cudaGetSymbolAddress((void**)&IB, g_ibuf);

    float* H    = FB + OFF_H;
    float* Y    = FB + OFF_Y;
    float* QKV  = FB + OFF_QKV;
    float* AT   = FB + OFF_ATTN;
    float* HID  = FB + OFF_HID;
    float* MO   = FB + OFF_MOE;
    float* CLSB = FB + OFF_CLS;
    float* PB   = FB + OFF_PATCH;
    float* SCB  = FB + OFF_SCALE;
    int* CNT  = IB;
    int* LIST = IB + 8;
    int* CROW = IB + 8 + 8 * 1576;

    cudaFuncSetAttribute(attn_kernel, cudaFuncAttributeMaxDynamicSharedMemorySize, ATT_SMEM);

    const int T = (int)Tt;

    // patch embed
    patchify_kernel<<<Bb * NP, 256>>>(X, PB);
    launch_gemm(PB, 0, Dm, Wpatch, 0, Dm, Bpatch, 0,
                AT, 0, Dm, Bb * NP, nullptr, Dm, Dm,
                nullptr, 0, nullptr, 0, nullptr, 0, /*epi*/0, 1);
    assemble_kernel<<<T, 256>>>(AT, Cls, Pos, H);

    for (int i = 0; i < 4; i++) {
        // attention block
        ln_kernel<<<T, 256>>>(H, Ln1g + i * Dm, Ln1b + i * Dm, Y, 1);
        launch_gemm(Y, 0, Dm, Wqkv + (long)i * Dm * 3 * Dm, 0, 3 * Dm, nullptr, 0,
                    QKV, 0, 3 * Dm, T, nullptr, 3 * Dm, Dm,
                    nullptr, 0, nullptr, 0, nullptr, 0, 0, 1);
        attn_kernel<<<dim3(NHd, Bb), 256, ATT_SMEM>>>(QKV, AT);
        launch_gemm(AT, 0, Dm, Wproj + (long)i * Dm * Dm, 0, Dm, Bproj + (long)i * Dm, 0,
                    H, 0, Dm, T, nullptr, Dm, Dm,
                    nullptr, 0, nullptr, 0, nullptr, 0, /*+=*/1, 1);

        // MLP block
        ln_kernel<<<T, 256>>>(H, Ln2g + i * Dm, Ln2b + i * Dm, Y, 1);
        int j = i >> 1;
        if ((i & 1) == 0) {
            launch_gemm(Y, 0, Dm, Wfc1 + (long)j * Dm * HIDm, 0, HIDm,
                        Bfc1 + (long)j * HIDm, 0,
                        HID, 0, HIDm, T, nullptr, HIDm, Dm,
                        nullptr, 0, nullptr, 0, nullptr, 0, /*gelu*/2, 1);
            launch_gemm(HID, 0, HIDm, Wfc2 + (long)j * HIDm * Dm, 0, Dm,
                        Bfc2 + (long)j * Dm, 0,
                        H, 0, Dm, T, nullptr, Dm, HIDm,
                        nullptr, 0, nullptr, 0, nullptr, 0, /*+=*/1, 1);
        } else {
            zero_cnt_kernel<<<1, 8>>>(CNT);
            gate_kernel<<<(T + 7) / 8, 256>>>(Y, Wgate + (long)j * Dm * Em,
                                              CNT, LIST, CROW, SCB);
            // expert fc1 (gathered rows of Y) -> gelu -> HID[e]
            launch_gemm(Y, 0, Dm,
                        We1 + (long)j * Em * Dm * HIDm, (long)Dm * HIDm, HIDm,
                        Be1 + (long)j * Em * HIDm, HIDm,
                        HID, (long)T * HIDm, HIDm,
                        T, CNT, HIDm, Dm,
                        LIST, 1576, nullptr, 0, nullptr, 0, /*gelu*/2, Em);
            // expert fc2 -> scaled scatter into (token, slot) rows of MO
            launch_gemm(HID, (long)T * HIDm, HIDm,
                        We2 + (long)j * Em * HIDm * Dm, (long)HIDm * Dm, Dm,
                        Be2 + (long)j * Em * Dm, Dm,
                        MO, 0, Dm,
                        T, CNT, Dm, HIDm,
                        nullptr, 0, CROW, 1576, SCB, 1576, /*scatter*/3, Em);
            moe_combine_kernel<<<T, 256>>>(MO, H);
        }
    }

    // final LN on cls rows + head
    ln_kernel<<<Bb, 256>>>(H, Lnfg, Lnfb, CLSB, Nt);
    head_kernel<<<dim3(4, Bb), 256>>>(CLSB, Whead, Bhead, OUT);
}

// round 15
// speedup vs baseline: 2.0690x; 1.0046x over previous
#include <cuda_runtime.h>
#include <cuda_bf16.h>
#include <math.h>

// ---------------- constants ----------------
static constexpr int  Dm   = 768;
static constexpr int  NHd  = 12;
static constexpr int  HD   = 64;
static constexpr int  Nt   = 197;
static constexpr int  Bb   = 8;
static constexpr long Tt   = (long)Bb * Nt;       // 1576
static constexpr int  HIDm = 3072;
static constexpr int  Em   = 8;
static constexpr int  NP   = 196;

// float arena offsets
static constexpr long OFF_H     = 0;
static constexpr long OFF_Y     = OFF_H    + Tt * Dm;
static constexpr long OFF_QKV   = OFF_Y    + Tt * Dm;
static constexpr long OFF_ATTN  = OFF_QKV  + Tt * 3 * Dm;
static constexpr long OFF_HID   = OFF_ATTN + Tt * Dm;
static constexpr long OFF_MOE   = OFF_HID  + (long)Em * Tt * HIDm;
static constexpr long OFF_CLS   = OFF_MOE  + Tt * 2 * Dm;
static constexpr long OFF_PATCH = OFF_CLS  + (long)Bb * Dm;
static constexpr long OFF_SCALE = OFF_PATCH + (long)Bb * NP * Dm;
static constexpr long FTOTAL    = OFF_SCALE + (long)Em * Tt;

__device__ float g_fbuf[FTOTAL];
__device__ int   g_ibuf[8 + 2 * Em * 1576];

// ---------------- TF32 helpers ----------------
__device__ __forceinline__ unsigned f2tf(float f) {
    unsigned r;
    asm("cvt.rna.tf32.f32 %0, %1;" : "=r"(r) : "f"(f));
    return r;
}

#define MMA_TF32(d, aa, bb)                                                    \
    asm volatile(                                                              \
        "mma.sync.aligned.m16n8k8.row.col.f32.tf32.tf32.f32 "                  \
        "{%0,%1,%2,%3}, {%4,%5,%6,%7}, {%8,%9}, {%0,%1,%2,%3};"                \
        : "+f"(d[0]), "+f"(d[1]), "+f"(d[2]), "+f"(d[3])                       \
        : "r"(aa[0]), "r"(aa[1]), "r"(aa[2]), "r"(aa[3]),                      \
          "r"(bb[0]), "r"(bb[1]))

// ---------------- grouped GEMM params ----------------
struct GemmP {
    const float* A; const float* B; const float* bias; float* C;
    int lda, ldb, ldc;
    int M, N, K;
    long sAz, sBz, sbz, sCz;
    const int* cnt;                 // per-z M override (device)
    const int* arow;  long sArz;    // optional A row gather
    const int* crow;  long sCrz;    // optional C row scatter
    const float* rsc; long sRz;     // optional per-row scale (epi 3)
    int epi;                        // 0 store, 1 +=, 2 gelu-store, 3 scale-scatter
};

// TF32 tensor-core GEMM: block 128x128, warp 32x64, K-stage 16.
__global__ __launch_bounds__(256)
void gemm_tf32(GemmP p)
{
    __shared__ unsigned As[16][136];   // [k][m], pad 136 -> conflict-free frag loads
    __shared__ unsigned Bs[16][136];   // [k][n]

    int z  = blockIdx.z;
    int Mz = p.cnt ? p.cnt[z] : p.M;
    int m0 = blockIdx.y * 128;
    if (m0 >= Mz) return;
    int n0 = blockIdx.x * 128;

    const float* A = p.A + z * p.sAz;
    const float* B = p.B + z * p.sBz;
    const int* arow = p.arow ? (p.arow + z * p.sArz) : nullptr;

    int tid = threadIdx.x;

    // A loader: row ma = tid>>1, k-offset ka = (tid&1)*8 (two float4 along k)
    int ma = tid >> 1;
    int ka = (tid & 1) << 3;
    int rg = m0 + ma;
    bool av = rg < Mz;
    long arw = av ? (arow ? (long)arow[rg] : (long)rg) : 0;
    const float* Ap = A + arw * p.lda + ka;

    // B loader: kb = tid>>4 (0..15), n = (tid&15)*4 and +64 (two float4 along n)
    int kb  = tid >> 4;
    int nbq = (tid & 15) << 2;
    const float* Bp = B + (long)kb * p.ldb + n0 + nbq;

    float4 zf = make_float4(0.f, 0.f, 0.f, 0.f);
    float4 a0 = zf, a1 = zf;
    if (av) { a0 = *(const float4*)Ap; a1 = *(const float4*)(Ap + 4); }
    float4 b0 = *(const float4*)Bp;
    float4 b1 = *(const float4*)(Bp + 64);

    float acc[2][8][4];
#pragma unroll
    for (int i = 0; i < 2; i++)
#pragma unroll
        for (int j = 0; j < 8; j++)
#pragma unroll
            for (int q = 0; q < 4; q++) acc[i][j][q] = 0.f;

    int warp = tid >> 5, lane = tid & 31;
    int wm = (warp & 3) << 5;        // 0,32,64,96
    int wn = (warp >> 2) << 6;       // 0,64
    int qr = lane >> 2;              // 0..7
    int qk = lane & 3;               // 0..3

    int nsteps = p.K >> 4;
    for (int s = 0; s < nsteps; ++s) {
        // stage registers -> smem (converted to tf32)
        As[ka + 0][ma] = f2tf(a0.x);
        As[ka + 1][ma] = f2tf(a0.y);
        As[ka + 2][ma] = f2tf(a0.z);
        As[ka + 3][ma] = f2tf(a0.w);
        As[ka + 4][ma] = f2tf(a1.x);
        As[ka + 5][ma] = f2tf(a1.y);
        As[ka + 6][ma] = f2tf(a1.z);
        As[ka + 7][ma] = f2tf(a1.w);
        *(uint4*)&Bs[kb][nbq]      = make_uint4(f2tf(b0.x), f2tf(b0.y), f2tf(b0.z), f2tf(b0.w));
        *(uint4*)&Bs[kb][nbq + 64] = make_uint4(f2tf(b1.x), f2tf(b1.y), f2tf(b1.z), f2tf(b1.w));
        __syncthreads();

        if (s + 1 < nsteps) {
            if (av) {
                a0 = *(const float4*)(Ap + (long)(s + 1) * 16);
                a1 = *(const float4*)(Ap + (long)(s + 1) * 16 + 4);
            }
            b0 = *(const float4*)(Bp + (long)(s + 1) * 16 * p.ldb);
            b1 = *(const float4*)(Bp + (long)(s + 1) * 16 * p.ldb + 64);
        }

#pragma unroll
        for (int kk = 0; kk < 16; kk += 8) {
            unsigned af[2][4];
#pragma unroll
            for (int mt = 0; mt < 2; mt++) {
                int mr = wm + mt * 16 + qr;
                af[mt][0] = As[kk + qk    ][mr];
                af[mt][1] = As[kk + qk    ][mr + 8];
                af[mt][2] = As[kk + qk + 4][mr];
                af[mt][3] = As[kk + qk + 4][mr + 8];
            }
            unsigned bfg[8][2];
#pragma unroll
            for (int nt = 0; nt < 8; nt++) {
                int nc = wn + nt * 8 + qr;
                bfg[nt][0] = Bs[kk + qk    ][nc];
                bfg[nt][1] = Bs[kk + qk + 4][nc];
            }
#pragma unroll
            for (int mt = 0; mt < 2; mt++)
#pragma unroll
                for (int nt = 0; nt < 8; nt++)
                    MMA_TF32(acc[mt][nt], af[mt], bfg[nt]);
        }
        __syncthreads();
    }

    // ---------------- epilogue ----------------
    float* C = p.C + z * p.sCz;
    const float* bias = p.bias ? (p.bias + z * p.sbz) : nullptr;
    const int*   crow = p.crow ? (p.crow + z * p.sCrz) : nullptr;
    const float* rsc  = p.rsc  ? (p.rsc  + z * p.sRz)  : nullptr;

#pragma unroll
    for (int mt = 0; mt < 2; mt++) {
#pragma unroll
        for (int half = 0; half < 2; half++) {
            int r = m0 + wm + mt * 16 + qr + half * 8;
            if (r >= Mz) continue;
            long cr = crow ? (long)crow[r] : (long)r;
            float sc = rsc ? rsc[r] : 1.0f;
            float* crp = C + cr * p.ldc;
#pragma unroll
            for (int nt = 0; nt < 8; nt++) {
                int c = n0 + wn + nt * 8 + qk * 2;
                float v0 = acc[mt][nt][half * 2 + 0];
                float v1 = acc[mt][nt][half * 2 + 1];
                if (bias) { v0 += bias[c]; v1 += bias[c + 1]; }
                if (p.epi == 2) {
                    v0 = 0.5f * v0 * (1.0f + erff(v0 * 0.70710678118654752f));
                    v1 = 0.5f * v1 * (1.0f + erff(v1 * 0.70710678118654752f));
                }
                float* cp = crp + c;
                if (p.epi == 1) {
                    float2 old = *(float2*)cp;
                    *(float2*)cp = make_float2(old.x + v0, old.y + v1);
                } else {
                    *(float2*)cp = make_float2(v0 * sc, v1 * sc);
                }
            }
        }
    }
}

// ---------------- patchify ----------------
__global__ void patchify_kernel(const float* __restrict__ x, float* __restrict__ P)
{
    int row = blockIdx.x;              // b*196 + pidx
    int b = row / NP, pidx = row % NP;
    int gy = pidx / 14, gx = pidx % 14;
    for (int k = threadIdx.x; k < Dm; k += 256) {
        int c = k >> 8, rem = k & 255, py = rem >> 4, px = rem & 15;
        P[(long)row * Dm + k] =
            x[((long)(b * 3 + c) * 224 + gy * 16 + py) * 224 + gx * 16 + px];
    }
}

// ---------------- assemble tokens (cls + pos) ----------------
__global__ void assemble_kernel(const float* __restrict__ tok, const float* __restrict__ cls,
                                const float* __restrict__ pos, float* __restrict__ h)
{
    int t = blockIdx.x;
    int b = t / Nt, n = t % Nt;
    for (int c = threadIdx.x; c < Dm; c += 256) {
        float v = (n == 0) ? cls[c] : tok[(long)(b * NP + n - 1) * Dm + c];
        h[(long)t * Dm + c] = v + pos[(long)n * Dm + c];
    }
}

// ---------------- layernorm (768 wide, 256 threads) ----------------
__global__ void ln_kernel(const float* __restrict__ x, const float* __restrict__ g,
                          const float* __restrict__ bb, float* __restrict__ y, int row_mul)
{
    int ro = blockIdx.x;
    const float* xr = x + (long)ro * row_mul * Dm;
    float* yr = y + (long)ro * Dm;
    int tid = threadIdx.x;
    float v0 = xr[tid], v1 = xr[tid + 256], v2 = xr[tid + 512];
    float s  = v0 + v1 + v2;
    float ss = v0 * v0 + v1 * v1 + v2 * v2;
#pragma unroll
    for (int off = 16; off; off >>= 1) {
        s  += __shfl_xor_sync(0xffffffffu, s,  off);
        ss += __shfl_xor_sync(0xffffffffu, ss, off);
    }
    __shared__ float sh[16];
    __shared__ float stat[2];
    int w = tid >> 5, l = tid & 31;
    if (l == 0) { sh[w] = s; sh[8 + w] = ss; }
    __syncthreads();
    if (tid == 0) {
        float S = 0.f, SS = 0.f;
        for (int i = 0; i < 8; i++) { S += sh[i]; SS += sh[8 + i]; }
        float m = S * (1.0f / 768.0f);
        float var = SS * (1.0f / 768.0f) - m * m;
        stat[0] = m;
        stat[1] = rsqrtf(var + 1e-5f);
    }
    __syncthreads();
    float m = stat[0], r = stat[1];
    yr[tid]       = (v0 - m) * r * g[tid]       + bb[tid];
    yr[tid + 256] = (v1 - m) * r * g[tid + 256] + bb[tid + 256];
    yr[tid + 512] = (v2 - m) * r * g[tid + 512] + bb[tid + 512];
}

// ---------------- attention (per (head, batch) block) ----------------
static constexpr int ATT_SMEM = (2 * Nt * HD + 8 * 208) * 4;   // ~107.5 KB

__global__ void attn_kernel(const float* __restrict__ qkv, float* __restrict__ out)
{
    extern __shared__ float sm[];
    float* Ks = sm;
    float* Vs = sm + Nt * HD;
    float* Ps = sm + 2 * Nt * HD;

    int h = blockIdx.x, b = blockIdx.y;
    int tid = threadIdx.x;

    for (int idx = tid; idx < Nt * 16; idx += 256) {
        int n = idx >> 4, d4 = (idx & 15) << 2;
        const float* base = qkv + (long)(b * Nt + n) * (3 * Dm) + h * HD + d4;
        *(float4*)&Ks[n * HD + d4] = *(const float4*)(base + Dm);
        *(float4*)&Vs[n * HD + d4] = *(const float4*)(base + 2 * Dm);
    }
    __syncthreads();

    int warp = tid >> 5, lane = tid & 31;
    float* pr = Ps + warp * 208;

    for (int r = warp; r < Nt; r += 8) {
        const float* qg = qkv + (long)(b * Nt + r) * (3 * Dm) + h * HD;
        float q[HD];
#pragma unroll
        for (int d4 = 0; d4 < HD; d4 += 4)
            *(float4*)&q[d4] = *(const float4*)(qg + d4);

        float mx = -1e30f;
        for (int j = lane; j < Nt; j += 32) {
            const float* kr = Ks + j * HD;
            float sv = 0.f;
#pragma unroll
            for (int d4 = 0; d4 < HD; d4 += 4) {
                float4 k4 = *(const float4*)(kr + d4);
                sv += q[d4] * k4.x + q[d4 + 1] * k4.y + q[d4 + 2] * k4.z + q[d4 + 3] * k4.w;
            }
            sv *= 0.125f;
            pr[j] = sv;
            mx = fmaxf(mx, sv);
        }
#pragma unroll
        for (int off = 16; off; off >>= 1)
            mx = fmaxf(mx, __shfl_xor_sync(0xffffffffu, mx, off));

        __syncwarp();
        float sum = 0.f;
        for (int j = lane; j < Nt; j += 32) {
            float pv = expf(pr[j] - mx);
            pr[j] = pv;
            sum += pv;
        }
#pragma unroll
        for (int off = 16; off; off >>= 1)
            sum += __shfl_xor_sync(0xffffffffu, sum, off);
        __syncwarp();

        float inv = 1.0f / sum;
        float o0 = 0.f, o1 = 0.f;
        for (int j = 0; j < Nt; j++) {
            float pv = pr[j];
            o0 += pv * Vs[j * HD + lane];
            o1 += pv * Vs[j * HD + lane + 32];
        }
        float* op = out + (long)(b * Nt + r) * Dm + h * HD;
        op[lane]      = o0 * inv;
        op[lane + 32] = o1 * inv;
        __syncwarp();
    }
}

// ---------------- MoE gate + routing ----------------
__global__ void zero_cnt_kernel(int* c) { if (threadIdx.x < 8) c[threadIdx.x] = 0; }

__global__ void gate_kernel(const float* __restrict__ y, const float* __restrict__ wg,
                            int* cnt, int* list, int* crow, float* scale)
{
    int warp = threadIdx.x >> 5, lane = threadIdx.x & 31;
    int t = blockIdx.x * 8 + warp;
    if (t >= (int)Tt) return;
    float lg[8] = {0, 0, 0, 0, 0, 0, 0, 0};
    const float* yr = y + (long)t * Dm;
    for (int d = lane; d < Dm; d += 32) {
        float xv = yr[d];
        const float* w = wg + d * Em;
#pragma unroll
        for (int e = 0; e < 8; e++) lg[e] += xv * w[e];
    }
#pragma unroll
    for (int e = 0; e < 8; e++)
#pragma unroll
        for (int off = 16; off; off >>= 1)
            lg[e] += __shfl_xor_sync(0xffffffffu, lg[e], off);
    if (lane == 0) {
        int e0 = 0; float v0 = lg[0];
        for (int e = 1; e < 8; e++) if (lg[e] > v0) { v0 = lg[e]; e0 = e; }
        int e1 = (e0 == 0) ? 1 : 0; float v1 = lg[e1];
        for (int e = 0; e < 8; e++)
            if (e != e0 && lg[e] > v1) { v1 = lg[e]; e1 = e; }
        float p0 = 1.0f / (1.0f + expf(v1 - v0));
        float p1 = 1.0f - p0;
        int pos = atomicAdd(&cnt[e0], 1);
        list[e0 * 1576 + pos] = t; crow[e0 * 1576 + pos] = t * 2;     scale[e0 * 1576 + pos] = p0;
        pos = atomicAdd(&cnt[e1], 1);
        list[e1 * 1576 + pos] = t; crow[e1 * 1576 + pos] = t * 2 + 1; scale[e1 * 1576 + pos] = p1;
    }
}

__global__ void moe_combine_kernel(const float* __restrict__ mo, float* __restrict__ h)
{
    long t = blockIdx.x;
    for (int c = threadIdx.x; c < Dm; c += 256)
        h[t * Dm + c] += mo[t * 2 * Dm + c] + mo[t * 2 * Dm + Dm + c];
}

// ---------------- head ----------------
__global__ void head_kernel(const float* __restrict__ cls, const float* __restrict__ w,
                            const float* __restrict__ bh, float* __restrict__ out)
{
    int c = blockIdx.x * 256 + threadIdx.x;
    int b = blockIdx.y;
    if (c >= 1000) return;
    const float* cr = cls + (long)b * Dm;
    float s0 = 0.f, s1 = 0.f, s2 = 0.f, s3 = 0.f;
    for (int d = 0; d < Dm; d += 4) {
        s0 += cr[d]     * w[(long)d * 1000 + c];
        s1 += cr[d + 1] * w[(long)(d + 1) * 1000 + c];
        s2 += cr[d + 2] * w[(long)(d + 2) * 1000 + c];
        s3 += cr[d + 3] * w[(long)(d + 3) * 1000 + c];
    }
    out[(long)b * 1000 + c] = (s0 + s1) + (s2 + s3) + bh[c];
}

// ---------------- host-side launcher ----------------
static inline void launch_gemm(const float* A, long sAz, int lda,
                               const float* B, long sBz, int ldb,
                               const float* bias, long sbz,
                               float* C, long sCz, int ldc,
                               int M, const int* cnt, int N, int K,
                               const int* arow, long sArz,
                               const int* crow, long sCrz,
                               const float* rsc, long sRz,
                               int epi, int Z)
{
    GemmP p;
    p.A = A; p.B = B; p.bias = bias; p.C = C;
    p.lda = lda; p.ldb = ldb; p.ldc = ldc;
    p.M = M; p.N = N; p.K = K;
    p.sAz = sAz; p.sBz = sBz; p.sbz = sbz; p.sCz = sCz;
    p.cnt = cnt;
    p.arow = arow; p.sArz = sArz;
    p.crow = crow; p.sCrz = sCrz;
    p.rsc = rsc;  p.sRz  = sRz;
    p.epi = epi;
    dim3 grid(N / 128, (M + 127) / 128, Z);
    gemm_tf32<<<grid, 256>>>(p);
}

extern "C" void kernel_launch(void* const* d_in, const int* in_sizes, int n_in,
                              void* d_out, int out_size)
{
    const float* X      = (const float*)d_in[0];
    const float* Wpatch = (const float*)d_in[1];
    const float* Bpatch = (const float*)d_in[2];
    const float* Cls    = (const float*)d_in[3];
    const float* Pos    = (const float*)d_in[4];
    const float* Ln1g   = (const float*)d_in[5];
    const float* Ln1b   = (const float*)d_in[6];
    const float* Wqkv   = (const float*)d_in[7];
    const float* Wproj  = (const float*)d_in[8];
    const float* Bproj  = (const float*)d_in[9];
    const float* Ln2g   = (const float*)d_in[10];
    const float* Ln2b   = (const float*)d_in[11];
    const float* Wfc1   = (const float*)d_in[12];
    const float* Bfc1   = (const float*)d_in[13];
    const float* Wfc2   = (const float*)d_in[14];
    const float* Bfc2   = (const float*)d_in[15];
    const float* Wgate  = (const float*)d_in[16];
    const float* We1    = (const float*)d_in[17];
    const float* Be1    = (const float*)d_in[18];
    const float* We2    = (const float*)d_in[19];
    const float* Be2    = (const float*)d_in[20];
    const float* Lnfg   = (const float*)d_in[21];
    const float* Lnfb   = (const float*)d_in[22];
    const float* Whead  = (const float*)d_in[23];
    const float* Bhead  = (const float*)d_in[24];
    float* OUT = (float*)d_out;

    float* FB = nullptr; int* IB = nullptr;
    cudaGetSymbolAddress((void**)&FB, g_fbuf);
    cudaGetSymbolAddress((void**)&IB, g_ibuf);

    float* H    = FB + OFF_H;
    float* Y    = FB + OFF_Y;
    float* QKV  = FB + OFF_QKV;
    float* AT   = FB + OFF_ATTN;
    float* HID  = FB + OFF_HID;
    float* MO   = FB + OFF_MOE;
    float* CLSB = FB + OFF_CLS;
    float* PB   = FB + OFF_PATCH;
    float* SCB  = FB + OFF_SCALE;
    int* CNT  = IB;
    int* LIST = IB + 8;
    int* CROW = IB + 8 + 8 * 1576;

    cudaFuncSetAttribute(attn_kernel, cudaFuncAttributeMaxDynamicSharedMemorySize, ATT_SMEM);

    const int T = (int)Tt;

    // patch embed
    patchify_kernel<<<Bb * NP, 256>>>(X, PB);
    launch_gemm(PB, 0, Dm, Wpatch, 0, Dm, Bpatch, 0,
                AT, 0, Dm, Bb * NP, nullptr, Dm, Dm,
                nullptr, 0, nullptr, 0, nullptr, 0, /*epi*/0, 1);
    assemble_kernel<<<T, 256>>>(AT, Cls, Pos, H);

    for (int i = 0; i < 4; i++) {
        // attention block
        ln_kernel<<<T, 256>>>(H, Ln1g + i * Dm, Ln1b + i * Dm, Y, 1);
        launch_gemm(Y, 0, Dm, Wqkv + (long)i * Dm * 3 * Dm, 0, 3 * Dm, nullptr, 0,
                    QKV, 0, 3 * Dm, T, nullptr, 3 * Dm, Dm,
                    nullptr, 0, nullptr, 0, nullptr, 0, 0, 1);
        attn_kernel<<<dim3(NHd, Bb), 256, ATT_SMEM>>>(QKV, AT);
        launch_gemm(AT, 0, Dm, Wproj + (long)i * Dm * Dm, 0, Dm, Bproj + (long)i * Dm, 0,
                    H, 0, Dm, T, nullptr, Dm, Dm,
                    nullptr, 0, nullptr, 0, nullptr, 0, /*+=*/1, 1);

        // MLP block
        ln_kernel<<<T, 256>>>(H, Ln2g + i * Dm, Ln2b + i * Dm, Y, 1);
        int j = i >> 1;
        if ((i & 1) == 0) {
            launch_gemm(Y, 0, Dm, Wfc1 + (long)j * Dm * HIDm, 0, HIDm,
                        Bfc1 + (long)j * HIDm, 0,
                        HID, 0, HIDm, T, nullptr, HIDm, Dm,
                        nullptr, 0, nullptr, 0, nullptr, 0, /*gelu*/2, 1);
            launch_gemm(HID, 0, HIDm, Wfc2 + (long)j * HIDm * Dm, 0, Dm,
                        Bfc2 + (long)j * Dm, 0,
                        H, 0, Dm, T, nullptr, Dm, HIDm,
                        nullptr, 0, nullptr, 0, nullptr, 0, /*+=*/1, 1);
        } else {
            zero_cnt_kernel<<<1, 8>>>(CNT);
            gate_kernel<<<(T + 7) / 8, 256>>>(Y, Wgate + (long)j * Dm * Em,
                                              CNT, LIST, CROW, SCB);
            // expert fc1 (gathered rows of Y) -> gelu -> HID[e]
            launch_gemm(Y, 0, Dm,
                        We1 + (long)j * Em * Dm * HIDm, (long)Dm * HIDm, HIDm,
                        Be1 + (long)j * Em * HIDm, HIDm,
                        HID, (long)T * HIDm, HIDm,
                        T, CNT, HIDm, Dm,
                        LIST, 1576, nullptr, 0, nullptr, 0, /*gelu*/2, Em);
            // expert fc2 -> scaled scatter into (token, slot) rows of MO
            launch_gemm(HID, (long)T * HIDm, HIDm,
                        We2 + (long)j * Em * HIDm * Dm, (long)HIDm * Dm, Dm,
                        Be2 + (long)j * Em * Dm, Dm,
                        MO, 0, Dm,
                        T, CNT, Dm, HIDm,
                        nullptr, 0, CROW, 1576, SCB, 1576, /*scatter*/3, Em);
            moe_combine_kernel<<<T, 256>>>(MO, H);
        }
    }

    // final LN on cls rows + head
    ln_kernel<<<Bb, 256>>>(H, Lnfg, Lnfb, CLSB, Nt);
    head_kernel<<<dim3(4, Bb), 256>>>(CLSB, Whead, Bhead, OUT);
}

// round 16
// speedup vs baseline: 2.0690x; 1.0000x over previous
#include <cuda_runtime.h>
#include <cuda_bf16.h>
#include <math.h>

// ---------------- constants ----------------
static constexpr int  Dm   = 768;
static constexpr int  NHd  = 12;
static constexpr int  HD   = 64;
static constexpr int  Nt   = 197;
static constexpr int  Bb   = 8;
static constexpr long Tt   = (long)Bb * Nt;       // 1576
static constexpr int  HIDm = 3072;
static constexpr int  Em   = 8;
static constexpr int  NP   = 196;

// float arena offsets
static constexpr long OFF_H     = 0;
static constexpr long OFF_Y     = OFF_H    + Tt * Dm;
static constexpr long OFF_QKV   = OFF_Y    + Tt * Dm;
static constexpr long OFF_ATTN  = OFF_QKV  + Tt * 3 * Dm;
static constexpr long OFF_HID   = OFF_ATTN + Tt * Dm;
static constexpr long OFF_MOE   = OFF_HID  + (long)Em * Tt * HIDm;
static constexpr long OFF_CLS   = OFF_MOE  + Tt * 2 * Dm;
static constexpr long OFF_PATCH = OFF_CLS  + (long)Bb * Dm;
static constexpr long OFF_SCALE = OFF_PATCH + (long)Bb * NP * Dm;
static constexpr long FTOTAL    = OFF_SCALE + (long)Em * Tt;

__device__ float g_fbuf[FTOTAL];
__device__ int   g_ibuf[8 + 2 * Em * 1576];

// ---------------- TF32 helpers ----------------
__device__ __forceinline__ unsigned f2tf(float f) {
    unsigned r;
    asm("cvt.rna.tf32.f32 %0, %1;" : "=r"(r) : "f"(f));
    return r;
}

#define MMA_TF32(d, aa, bb)                                                    \
    asm volatile(                                                              \
        "mma.sync.aligned.m16n8k8.row.col.f32.tf32.tf32.f32 "                  \
        "{%0,%1,%2,%3}, {%4,%5,%6,%7}, {%8,%9}, {%0,%1,%2,%3};"                \
        : "+f"(d[0]), "+f"(d[1]), "+f"(d[2]), "+f"(d[3])                       \
        : "r"(aa[0]), "r"(aa[1]), "r"(aa[2]), "r"(aa[3]),                      \
          "r"(bb[0]), "r"(bb[1]))

// ---------------- grouped GEMM params ----------------
struct GemmP {
    const float* A; const float* B; const float* bias; float* C;
    int lda, ldb, ldc;
    int M, N, K;
    long sAz, sBz, sbz, sCz;
    const int* cnt;                 // per-z M override (device)
    const int* arow;  long sArz;    // optional A row gather
    const int* crow;  long sCrz;    // optional C row scatter
    const float* rsc; long sRz;     // optional per-row scale (epi 3)
    int epi;                        // 0 store, 1 +=, 2 gelu-store, 3 scale-scatter
};

// TF32 tensor-core GEMM: block 128x128, warp 32x64, K-stage 16,
// 2-stage smem double buffer, one __syncthreads per stage, 2 CTAs/SM.
__global__ __launch_bounds__(256, 2)
void gemm_tf32(GemmP p)
{
    __shared__ unsigned As[2][16][136];   // [buf][k][m]
    __shared__ unsigned Bs[2][16][136];   // [buf][k][n]

    int z  = blockIdx.z;
    int Mz = p.cnt ? p.cnt[z] : p.M;
    int m0 = blockIdx.y * 128;
    if (m0 >= Mz) return;
    int n0 = blockIdx.x * 128;

    const float* A = p.A + z * p.sAz;
    const float* B = p.B + z * p.sBz;
    const int* arow = p.arow ? (p.arow + z * p.sArz) : nullptr;

    int tid = threadIdx.x;

    // A loader: row ma = tid>>1, k-offset ka = (tid&1)*8 (two float4 along k)
    int ma = tid >> 1;
    int ka = (tid & 1) << 3;
    int rg = m0 + ma;
    bool av = rg < Mz;
    long arw = av ? (arow ? (long)arow[rg] : (long)rg) : 0;
    const float* Ap = A + arw * p.lda + ka;

    // B loader: kb = tid>>4 (0..15), n = (tid&15)*4 and +64 (two float4 along n)
    int kb  = tid >> 4;
    int nbq = (tid & 15) << 2;
    const float* Bp = B + (long)kb * p.ldb + n0 + nbq;

    float4 zf = make_float4(0.f, 0.f, 0.f, 0.f);
    float4 a0 = zf, a1 = zf;
    if (av) { a0 = *(const float4*)Ap; a1 = *(const float4*)(Ap + 4); }
    float4 b0 = *(const float4*)Bp;
    float4 b1 = *(const float4*)(Bp + 64);

    float acc[2][8][4];
#pragma unroll
    for (int i = 0; i < 2; i++)
#pragma unroll
        for (int j = 0; j < 8; j++)
#pragma unroll
            for (int q = 0; q < 4; q++) acc[i][j][q] = 0.f;

    int warp = tid >> 5, lane = tid & 31;
    int wm = (warp & 3) << 5;        // 0,32,64,96
    int wn = (warp >> 2) << 6;       // 0,64
    int qr = lane >> 2;              // 0..7
    int qk = lane & 3;               // 0..3

    // stage 0 -> buf 0
    As[0][ka + 0][ma] = f2tf(a0.x);
    As[0][ka + 1][ma] = f2tf(a0.y);
    As[0][ka + 2][ma] = f2tf(a0.z);
    As[0][ka + 3][ma] = f2tf(a0.w);
    As[0][ka + 4][ma] = f2tf(a1.x);
    As[0][ka + 5][ma] = f2tf(a1.y);
    As[0][ka + 6][ma] = f2tf(a1.z);
    As[0][ka + 7][ma] = f2tf(a1.w);
    *(uint4*)&Bs[0][kb][nbq]      = make_uint4(f2tf(b0.x), f2tf(b0.y), f2tf(b0.z), f2tf(b0.w));
    *(uint4*)&Bs[0][kb][nbq + 64] = make_uint4(f2tf(b1.x), f2tf(b1.y), f2tf(b1.z), f2tf(b1.w));
    __syncthreads();

    int nsteps = p.K >> 4;
    for (int s = 0; s < nsteps; ++s) {
        int cur = s & 1;
        bool more = (s + 1 < nsteps);

        if (more) {
            if (av) {
                a0 = *(const float4*)(Ap + (long)(s + 1) * 16);
                a1 = *(const float4*)(Ap + (long)(s + 1) * 16 + 4);
            }
            b0 = *(const float4*)(Bp + (long)(s + 1) * 16 * p.ldb);
            b1 = *(const float4*)(Bp + (long)(s + 1) * 16 * p.ldb + 64);
        }

#pragma unroll
        for (int kk = 0; kk < 16; kk += 8) {
            unsigned af[2][4];
#pragma unroll
            for (int mt = 0; mt < 2; mt++) {
                int mr = wm + mt * 16 + qr;
                af[mt][0] = As[cur][kk + qk    ][mr];
                af[mt][1] = As[cur][kk + qk    ][mr + 8];
                af[mt][2] = As[cur][kk + qk + 4][mr];
                af[mt][3] = As[cur][kk + qk + 4][mr + 8];
            }
            unsigned bfg[8][2];
#pragma unroll
            for (int nt = 0; nt < 8; nt++) {
                int nc = wn + nt * 8 + qr;
                bfg[nt][0] = Bs[cur][kk + qk    ][nc];
                bfg[nt][1] = Bs[cur][kk + qk + 4][nc];
            }
#pragma unroll
            for (int mt = 0; mt < 2; mt++)
#pragma unroll
                for (int nt = 0; nt < 8; nt++)
                    MMA_TF32(acc[mt][nt], af[mt], bfg[nt]);
        }

        if (more) {
            int nxt = cur ^ 1;
            As[nxt][ka + 0][ma] = f2tf(a0.x);
            As[nxt][ka + 1][ma] = f2tf(a0.y);
            As[nxt][ka + 2][ma] = f2tf(a0.z);
            As[nxt][ka + 3][ma] = f2tf(a0.w);
            As[nxt][ka + 4][ma] = f2tf(a1.x);
            As[nxt][ka + 5][ma] = f2tf(a1.y);
            As[nxt][ka + 6][ma] = f2tf(a1.z);
            As[nxt][ka + 7][ma] = f2tf(a1.w);
            *(uint4*)&Bs[nxt][kb][nbq]      = make_uint4(f2tf(b0.x), f2tf(b0.y), f2tf(b0.z), f2tf(b0.w));
            *(uint4*)&Bs[nxt][kb][nbq + 64] = make_uint4(f2tf(b1.x), f2tf(b1.y), f2tf(b1.z), f2tf(b1.w));
        }
        __syncthreads();
    }

    // ---------------- epilogue ----------------
    float* C = p.C + z * p.sCz;
    const float* bias = p.bias ? (p.bias + z * p.sbz) : nullptr;
    const int*   crow = p.crow ? (p.crow + z * p.sCrz) : nullptr;
    const float* rsc  = p.rsc  ? (p.rsc  + z * p.sRz)  : nullptr;

#pragma unroll
    for (int mt = 0; mt < 2; mt++) {
#pragma unroll
        for (int half = 0; half < 2; half++) {
            int r = m0 + wm + mt * 16 + qr + half * 8;
            if (r >= Mz) continue;
            long cr = crow ? (long)crow[r] : (long)r;
            float sc = rsc ? rsc[r] : 1.0f;
            float* crp = C + cr * p.ldc;
#pragma unroll
            for (int nt = 0; nt < 8; nt++) {
                int c = n0 + wn + nt * 8 + qk * 2;
                float v0 = acc[mt][nt][half * 2 + 0];
                float v1 = acc[mt][nt][half * 2 + 1];
                if (bias) { v0 += bias[c]; v1 += bias[c + 1]; }
                if (p.epi == 2) {
                    v0 = 0.5f * v0 * (1.0f + erff(v0 * 0.70710678118654752f));
                    v1 = 0.5f * v1 * (1.0f + erff(v1 * 0.70710678118654752f));
                }
                float* cp = crp + c;
                if (p.epi == 1) {
                    float2 old = *(float2*)cp;
                    *(float2*)cp = make_float2(old.x + v0, old.y + v1);
                } else {
                    *(float2*)cp = make_float2(v0 * sc, v1 * sc);
                }
            }
        }
    }
}

// ---------------- patchify ----------------
__global__ void patchify_kernel(const float* __restrict__ x, float* __restrict__ P)
{
    int row = blockIdx.x;              // b*196 + pidx
    int b = row / NP, pidx = row % NP;
    int gy = pidx / 14, gx = pidx % 14;
    for (int k = threadIdx.x; k < Dm; k += 256) {
        int c = k >> 8, rem = k & 255, py = rem >> 4, px = rem & 15;
        P[(long)row * Dm + k] =
            x[((long)(b * 3 + c) * 224 + gy * 16 + py) * 224 + gx * 16 + px];
    }
}

// ---------------- assemble tokens (cls + pos) ----------------
__global__ void assemble_kernel(const float* __restrict__ tok, const float* __restrict__ cls,
                                const float* __restrict__ pos, float* __restrict__ h)
{
    int t = blockIdx.x;
    int b = t / Nt, n = t % Nt;
    for (int c = threadIdx.x; c < Dm; c += 256) {
        float v = (n == 0) ? cls[c] : tok[(long)(b * NP + n - 1) * Dm + c];
        h[(long)t * Dm + c] = v + pos[(long)n * Dm + c];
    }
}

// ---------------- layernorm (768 wide, 256 threads) ----------------
__global__ void ln_kernel(const float* __restrict__ x, const float* __restrict__ g,
                          const float* __restrict__ bb, float* __restrict__ y, int row_mul)
{
    int ro = blockIdx.x;
    const float* xr = x + (long)ro * row_mul * Dm;
    float* yr = y + (long)ro * Dm;
    int tid = threadIdx.x;
    float v0 = xr[tid], v1 = xr[tid + 256], v2 = xr[tid + 512];
    float s  = v0 + v1 + v2;
    float ss = v0 * v0 + v1 * v1 + v2 * v2;
#pragma unroll
    for (int off = 16; off; off >>= 1) {
        s  += __shfl_xor_sync(0xffffffffu, s,  off);
        ss += __shfl_xor_sync(0xffffffffu, ss, off);
    }
    __shared__ float sh[16];
    __shared__ float stat[2];
    int w = tid >> 5, l = tid & 31;
    if (l == 0) { sh[w] = s; sh[8 + w] = ss; }
    __syncthreads();
    if (tid == 0) {
        float S = 0.f, SS = 0.f;
        for (int i = 0; i < 8; i++) { S += sh[i]; SS += sh[8 + i]; }
        float m = S * (1.0f / 768.0f);
        float var = SS * (1.0f / 768.0f) - m * m;
        stat[0] = m;
        stat[1] = rsqrtf(var + 1e-5f);
    }
    __syncthreads();
    float m = stat[0], r = stat[1];
    yr[tid]       = (v0 - m) * r * g[tid]       + bb[tid];
    yr[tid + 256] = (v1 - m) * r * g[tid + 256] + bb[tid + 256];
    yr[tid + 512] = (v2 - m) * r * g[tid + 512] + bb[tid + 512];
}

// ---------------- attention (per (head, batch) block) ----------------
static constexpr int ATT_SMEM = (2 * Nt * HD + 8 * 208) * 4;   // ~107.5 KB

__global__ void attn_kernel(const float* __restrict__ qkv, float* __restrict__ out)
{
    extern __shared__ float sm[];
    float* Ks = sm;
    float* Vs = sm + Nt * HD;
    float* Ps = sm + 2 * Nt * HD;

    int h = blockIdx.x, b = blockIdx.y;
    int tid = threadIdx.x;

    for (int idx = tid; idx < Nt * 16; idx += 256) {
        int n = idx >> 4, d4 = (idx & 15) << 2;
        const float* base = qkv + (long)(b * Nt + n) * (3 * Dm) + h * HD + d4;
        *(float4*)&Ks[n * HD + d4] = *(const float4*)(base + Dm);
        *(float4*)&Vs[n * HD + d4] = *(const float4*)(base + 2 * Dm);
    }
    __syncthreads();

    int warp = tid >> 5, lane = tid & 31;
    float* pr = Ps + warp * 208;

    for (int r = warp; r < Nt; r += 8) {
        const float* qg = qkv + (long)(b * Nt + r) * (3 * Dm) + h * HD;
        float q[HD];
#pragma unroll
        for (int d4 = 0; d4 < HD; d4 += 4)
            *(float4*)&q[d4] = *(const float4*)(qg + d4);

        float mx = -1e30f;
        for (int j = lane; j < Nt; j += 32) {
            const float* kr = Ks + j * HD;
            float sv = 0.f;
#pragma unroll
            for (int d4 = 0; d4 < HD; d4 += 4) {
                float4 k4 = *(const float4*)(kr + d4);
                sv += q[d4] * k4.x + q[d4 + 1] * k4.y + q[d4 + 2] * k4.z + q[d4 + 3] * k4.w;
            }
            sv *= 0.125f;
            pr[j] = sv;
            mx = fmaxf(mx, sv);
        }
#pragma unroll
        for (int off = 16; off; off >>= 1)
            mx = fmaxf(mx, __shfl_xor_sync(0xffffffffu, mx, off));

        __syncwarp();
        float sum = 0.f;
        for (int j = lane; j < Nt; j += 32) {
            float pv = expf(pr[j] - mx);
            pr[j] = pv;
            sum += pv;
        }
#pragma unroll
        for (int off = 16; off; off >>= 1)
            sum += __shfl_xor_sync(0xffffffffu, sum, off);
        __syncwarp();

        float inv = 1.0f / sum;
        float o0 = 0.f, o1 = 0.f;
        for (int j = 0; j < Nt; j++) {
            float pv = pr[j];
            o0 += pv * Vs[j * HD + lane];
            o1 += pv * Vs[j * HD + lane + 32];
        }
        float* op = out + (long)(b * Nt + r) * Dm + h * HD;
        op[lane]      = o0 * inv;
        op[lane + 32] = o1 * inv;
        __syncwarp();
    }
}

// ---------------- MoE gate + routing ----------------
__global__ void zero_cnt_kernel(int* c) { if (threadIdx.x < 8) c[threadIdx.x] = 0; }

__global__ void gate_kernel(const float* __restrict__ y, const float* __restrict__ wg,
                            int* cnt, int* list, int* crow, float* scale)
{
    int warp = threadIdx.x >> 5, lane = threadIdx.x & 31;
    int t = blockIdx.x * 8 + warp;
    if (t >= (int)Tt) return;
    float lg[8] = {0, 0, 0, 0, 0, 0, 0, 0};
    const float* yr = y + (long)t * Dm;
    for (int d = lane; d < Dm; d += 32) {
        float xv = yr[d];
        const float* w = wg + d * Em;
#pragma unroll
        for (int e = 0; e < 8; e++) lg[e] += xv * w[e];
    }
#pragma unroll
    for (int e = 0; e < 8; e++)
#pragma unroll
        for (int off = 16; off; off >>= 1)
            lg[e] += __shfl_xor_sync(0xffffffffu, lg[e], off);
    if (lane == 0) {
        int e0 = 0; float v0 = lg[0];
        for (int e = 1; e < 8; e++) if (lg[e] > v0) { v0 = lg[e]; e0 = e; }
        int e1 = (e0 == 0) ? 1 : 0; float v1 = lg[e1];
        for (int e = 0; e < 8; e++)
            if (e != e0 && lg[e] > v1) { v1 = lg[e]; e1 = e; }
        float p0 = 1.0f / (1.0f + expf(v1 - v0));
        float p1 = 1.0f - p0;
        int pos = atomicAdd(&cnt[e0], 1);
        list[e0 * 1576 + pos] = t; crow[e0 * 1576 + pos] = t * 2;     scale[e0 * 1576 + pos] = p0;
        pos = atomicAdd(&cnt[e1], 1);
        list[e1 * 1576 + pos] = t; crow[e1 * 1576 + pos] = t * 2 + 1; scale[e1 * 1576 + pos] = p1;
    }
}

__global__ void moe_combine_kernel(const float* __restrict__ mo, float* __restrict__ h)
{
    long t = blockIdx.x;
    for (int c = threadIdx.x; c < Dm; c += 256)
        h[t * Dm + c] += mo[t * 2 * Dm + c] + mo[t * 2 * Dm + Dm + c];
}

// ---------------- head ----------------
__global__ void head_kernel(const float* __restrict__ cls, const float* __restrict__ w,
                            const float* __restrict__ bh, float* __restrict__ out)
{
    int c = blockIdx.x * 256 + threadIdx.x;
    int b = blockIdx.y;
    if (c >= 1000) return;
    const float* cr = cls + (long)b * Dm;
    float s0 = 0.f, s1 = 0.f, s2 = 0.f, s3 = 0.f;
    for (int d = 0; d < Dm; d += 4) {
        s0 += cr[d]     * w[(long)d * 1000 + c];
        s1 += cr[d + 1] * w[(long)(d + 1) * 1000 + c];
        s2 += cr[d + 2] * w[(long)(d + 2) * 1000 + c];
        s3 += cr[d + 3] * w[(long)(d + 3) * 1000 + c];
    }
    out[(long)b * 1000 + c] = (s0 + s1) + (s2 + s3) + bh[c];
}

// ---------------- host-side launcher ----------------
static inline void launch_gemm(const float* A, long sAz, int lda,
                               const float* B, long sBz, int ldb,
                               const float* bias, long sbz,
                               float* C, long sCz, int ldc,
                               int M, const int* cnt, int N, int K,
                               const int* arow, long sArz,
                               const int* crow, long sCrz,
                               const float* rsc, long sRz,
                               int epi, int Z)
{
    GemmP p;
    p.A = A; p.B = B; p.bias = bias; p.C = C;
    p.lda = lda; p.ldb = ldb; p.ldc = ldc;
    p.M = M; p.N = N; p.K = K;
    p.sAz = sAz; p.sBz = sBz; p.sbz = sbz; p.sCz = sCz;
    p.cnt = cnt;
    p.arow = arow; p.sArz = sArz;
    p.crow = crow; p.sCrz = sCrz;
    p.rsc = rsc;  p.sRz  = sRz;
    p.epi = epi;
    dim3 grid(N / 128, (M + 127) / 128, Z);
    gemm_tf32<<<grid, 256>>>(p);
}

extern "C" void kernel_launch(void* const* d_in, const int* in_sizes, int n_in,
                              void* d_out, int out_size)
{
    const float* X      = (const float*)d_in[0];
    const float* Wpatch = (const float*)d_in[1];
    const float* Bpatch = (const float*)d_in[2];
    const float* Cls    = (const float*)d_in[3];
    const float* Pos    = (const float*)d_in[4];
    const float* Ln1g   = (const float*)d_in[5];
    const float* Ln1b   = (const float*)d_in[6];
    const float* Wqkv   = (const float*)d_in[7];
    const float* Wproj  = (const float*)d_in[8];
    const float* Bproj  = (const float*)d_in[9];
    const float* Ln2g   = (const float*)d_in[10];
    const float* Ln2b   = (const float*)d_in[11];
    const float* Wfc1   = (const float*)d_in[12];
    const float* Bfc1   = (const float*)d_in[13];
    const float* Wfc2   = (const float*)d_in[14];
    const float* Bfc2   = (const float*)d_in[15];
    const float* Wgate  = (const float*)d_in[16];
    const float* We1    = (const float*)d_in[17];
    const float* Be1    = (const float*)d_in[18];
    const float* We2    = (const float*)d_in[19];
    const float* Be2    = (const float*)d_in[20];
    const float* Lnfg   = (const float*)d_in[21];
    const float* Lnfb   = (const float*)d_in[22];
    const float* Whead  = (const float*)d_in[23];
    const float* Bhead  = (const float*)d_in[24];
    float* OUT = (float*)d_out;

    float* FB = nullptr; int* IB = nullptr;
    cudaGetSymbolAddress((void**)&FB, g_fbuf);
    cudaGetSymbolAddress((void**)&IB, g_ibuf);

    float* H    = FB + OFF_H;
    float* Y    = FB + OFF_Y;
    float* QKV  = FB + OFF_QKV;
    float* AT   = FB + OFF_ATTN;
    float* HID  = FB + OFF_HID;
    float* MO   = FB + OFF_MOE;
    float* CLSB = FB + OFF_CLS;
    float* PB   = FB + OFF_PATCH;
    float* SCB  = FB + OFF_SCALE;
    int* CNT  = IB;
    int* LIST = IB + 8;
    int* CROW = IB + 8 + 8 * 1576;

    cudaFuncSetAttribute(attn_kernel, cudaFuncAttributeMaxDynamicSharedMemorySize, ATT_SMEM);

    const int T = (int)Tt;

    // patch embed
    patchify_kernel<<<Bb * NP, 256>>>(X, PB);
    launch_gemm(PB, 0, Dm, Wpatch, 0, Dm, Bpatch, 0,
                AT, 0, Dm, Bb * NP, nullptr, Dm, Dm,
                nullptr, 0, nullptr, 0, nullptr, 0, /*epi*/0, 1);
    assemble_kernel<<<T, 256>>>(AT, Cls, Pos, H);

    for (int i = 0; i < 4; i++) {
        // attention block
        ln_kernel<<<T, 256>>>(H, Ln1g + i * Dm, Ln1b + i * Dm, Y, 1);
        launch_gemm(Y, 0, Dm, Wqkv + (long)i * Dm * 3 * Dm, 0, 3 * Dm, nullptr, 0,
                    QKV, 0, 3 * Dm, T, nullptr, 3 * Dm, Dm,
                    nullptr, 0, nullptr, 0, nullptr, 0, 0, 1);
        attn_kernel<<<dim3(NHd, Bb), 256, ATT_SMEM>>>(QKV, AT);
        launch_gemm(AT, 0, Dm, Wproj + (long)i * Dm * Dm, 0, Dm, Bproj + (long)i * Dm, 0,
                    H, 0, Dm, T, nullptr, Dm, Dm,
                    nullptr, 0, nullptr, 0, nullptr, 0, /*+=*/1, 1);

        // MLP block
        ln_kernel<<<T, 256>>>(H, Ln2g + i * Dm, Ln2b + i * Dm, Y, 1);
        int j = i >> 1;
        if ((i & 1) == 0) {
            launch_gemm(Y, 0, Dm, Wfc1 + (long)j * Dm * HIDm, 0, HIDm,
                        Bfc1 + (long)j * HIDm, 0,
                        HID, 0, HIDm, T, nullptr, HIDm, Dm,
                        nullptr, 0, nullptr, 0, nullptr, 0, /*gelu*/2, 1);
            launch_gemm(HID, 0, HIDm, Wfc2 + (long)j * HIDm * Dm, 0, Dm,
                        Bfc2 + (long)j * Dm, 0,
                        H, 0, Dm, T, nullptr, Dm, HIDm,
                        nullptr, 0, nullptr, 0, nullptr, 0, /*+=*/1, 1);
        } else {
            zero_cnt_kernel<<<1, 8>>>(CNT);
            gate_kernel<<<(T + 7) / 8, 256>>>(Y, Wgate + (long)j * Dm * Em,
                                              CNT, LIST, CROW, SCB);
            // expert fc1 (gathered rows of Y) -> gelu -> HID[e]
            launch_gemm(Y, 0, Dm,
                        We1 + (long)j * Em * Dm * HIDm, (long)Dm * HIDm, HIDm,
                        Be1 + (long)j * Em * HIDm, HIDm,
                        HID, (long)T * HIDm, HIDm,
                        T, CNT, HIDm, Dm,
                        LIST, 1576, nullptr, 0, nullptr, 0, /*gelu*/2, Em);
            // expert fc2 -> scaled scatter into (token, slot) rows of MO
            launch_gemm(HID, (long)T * HIDm, HIDm,
                        We2 + (long)j * Em * HIDm * Dm, (long)HIDm * Dm, Dm,
                        Be2 + (long)j * Em * Dm, Dm,
                        MO, 0, Dm,
                        T, CNT, Dm, HIDm,
                        nullptr, 0, CROW, 1576, SCB, 1576, /*scatter*/3, Em);
            moe_combine_kernel<<<T, 256>>>(MO, H);
        }
    }

    // final LN on cls rows + head
    ln_kernel<<<Bb, 256>>>(H, Lnfg, Lnfb, CLSB, Nt);
    head_kernel<<<dim3(4, Bb), 256>>>(CLSB, Whead, Bhead, OUT);
}

// round 17
// speedup vs baseline: 2.3649x; 1.1430x over previous
#include <cuda_runtime.h>
#include <cuda_bf16.h>
#include <cuda_fp16.h>
#include <math.h>

// ---------------- constants ----------------
static constexpr int  Dm   = 768;
static constexpr int  NHd  = 12;
static constexpr int  HD   = 64;
static constexpr int  Nt   = 197;
static constexpr int  Bb   = 8;
static constexpr long Tt   = (long)Bb * Nt;       // 1576
static constexpr int  HIDm = 3072;
static constexpr int  Em   = 8;
static constexpr int  NP   = 196;

// float arena offsets
static constexpr long OFF_H     = 0;
static constexpr long OFF_Y     = OFF_H    + Tt * Dm;
static constexpr long OFF_QKV   = OFF_Y    + Tt * Dm;
static constexpr long OFF_ATTN  = OFF_QKV  + Tt * 3 * Dm;
static constexpr long OFF_HID   = OFF_ATTN + Tt * Dm;
static constexpr long OFF_MOE   = OFF_HID  + (long)Em * Tt * HIDm;
static constexpr long OFF_CLS   = OFF_MOE  + Tt * 2 * Dm;
static constexpr long OFF_PATCH = OFF_CLS  + (long)Bb * Dm;
static constexpr long OFF_SCALE = OFF_PATCH + (long)Bb * NP * Dm;
static constexpr long FTOTAL    = OFF_SCALE + (long)Em * Tt;

__device__ float g_fbuf[FTOTAL];
__device__ int   g_ibuf[8 + 2 * Em * 1576];

// ---------------- FP16 helpers ----------------
__device__ __forceinline__ unsigned pack_h2(float lo, float hi) {
    __half2 h = __floats2half2_rn(lo, hi);
    return *(unsigned*)&h;
}

#define MMA_F16(d, aa, bb)                                                     \
    asm volatile(                                                              \
        "mma.sync.aligned.m16n8k16.row.col.f32.f16.f16.f32 "                   \
        "{%0,%1,%2,%3}, {%4,%5,%6,%7}, {%8,%9}, {%0,%1,%2,%3};"                \
        : "+f"(d[0]), "+f"(d[1]), "+f"(d[2]), "+f"(d[3])                       \
        : "r"(aa[0]), "r"(aa[1]), "r"(aa[2]), "r"(aa[3]),                      \
          "r"(bb[0]), "r"(bb[1]))

// ---------------- grouped GEMM params ----------------
struct GemmP {
    const float* A; const float* B; const float* bias; float* C;
    int lda, ldb, ldc;
    int M, N, K;
    long sAz, sBz, sbz, sCz;
    const int* cnt;                 // per-z M override (device)
    const int* arow;  long sArz;    // optional A row gather
    const int* crow;  long sCrz;    // optional C row scatter
    const float* rsc; long sRz;     // optional per-row scale (epi 3)
    int epi;                        // 0 store, 1 +=, 2 gelu-store, 3 scale-scatter
};

// FP16 tensor-core GEMM: block 128x128, warp 32x64, K-stage 16 (one k16 MMA pass),
// half2-packed k-pairs in smem, 2-stage double buffer.
__global__ __launch_bounds__(256, 2)
void gemm_f16(GemmP p)
{
    // uint = half2 holding (k_even, k_odd); [buf][k/2][m or n]
    __shared__ unsigned As[2][8][136];
    __shared__ unsigned Bs[2][8][136];

    int z  = blockIdx.z;
    int Mz = p.cnt ? p.cnt[z] : p.M;
    int m0 = blockIdx.y * 128;
    if (m0 >= Mz) return;
    int n0 = blockIdx.x * 128;

    const float* A = p.A + z * p.sAz;
    const float* B = p.B + z * p.sBz;
    const int* arow = p.arow ? (p.arow + z * p.sArz) : nullptr;

    int tid = threadIdx.x;

    // A loader: row ma = tid>>1, k-offset ka = (tid&1)*8 (8 consecutive floats along k)
    int ma = tid >> 1;
    int ka = (tid & 1) << 3;          // 0 or 8 (element units)
    int rg = m0 + ma;
    bool av = rg < Mz;
    long arw = av ? (arow ? (long)arow[rg] : (long)rg) : 0;
    const float* Ap = A + arw * p.lda + ka;

    // B loader: kp = tid>>5 (0..7 k-pair), n = (tid&31)*4 (four columns)
    int kp = tid >> 5;
    int nb = (tid & 31) << 2;
    const float* Bp0 = B + (long)(2 * kp)     * p.ldb + n0 + nb;
    const float* Bp1 = B + (long)(2 * kp + 1) * p.ldb + n0 + nb;

    float4 zf = make_float4(0.f, 0.f, 0.f, 0.f);
    float4 a0 = zf, a1 = zf;
    if (av) { a0 = *(const float4*)Ap; a1 = *(const float4*)(Ap + 4); }
    float4 b0 = *(const float4*)Bp0;
    float4 b1 = *(const float4*)Bp1;

    float acc[2][8][4];
#pragma unroll
    for (int i = 0; i < 2; i++)
#pragma unroll
        for (int j = 0; j < 8; j++)
#pragma unroll
            for (int q = 0; q < 4; q++) acc[i][j][q] = 0.f;

    int warp = tid >> 5, lane = tid & 31;
    int wm = (warp & 3) << 5;        // 0,32,64,96
    int wn = (warp >> 2) << 6;       // 0,64
    int qr = lane >> 2;              // 0..7
    int qk = lane & 3;               // 0..3

    int ka2 = ka >> 1;               // 0 or 4 (k-pair units)

    // stage 0 -> buf 0
    As[0][ka2 + 0][ma] = pack_h2(a0.x, a0.y);
    As[0][ka2 + 1][ma] = pack_h2(a0.z, a0.w);
    As[0][ka2 + 2][ma] = pack_h2(a1.x, a1.y);
    As[0][ka2 + 3][ma] = pack_h2(a1.z, a1.w);
    *(uint4*)&Bs[0][kp][nb] = make_uint4(pack_h2(b0.x, b1.x), pack_h2(b0.y, b1.y),
                                         pack_h2(b0.z, b1.z), pack_h2(b0.w, b1.w));
    __syncthreads();

    int nsteps = p.K >> 4;
    for (int s = 0; s < nsteps; ++s) {
        int cur = s & 1;
        bool more = (s + 1 < nsteps);

        if (more) {
            if (av) {
                a0 = *(const float4*)(Ap + (long)(s + 1) * 16);
                a1 = *(const float4*)(Ap + (long)(s + 1) * 16 + 4);
            }
            b0 = *(const float4*)(Bp0 + (long)(s + 1) * 16 * p.ldb);
            b1 = *(const float4*)(Bp1 + (long)(s + 1) * 16 * p.ldb);
        }

        // one k16 MMA pass over the warp tile
        {
            unsigned af[2][4];
#pragma unroll
            for (int mt = 0; mt < 2; mt++) {
                int mr = wm + mt * 16 + qr;
                af[mt][0] = As[cur][qk    ][mr];
                af[mt][1] = As[cur][qk    ][mr + 8];
                af[mt][2] = As[cur][qk + 4][mr];
                af[mt][3] = As[cur][qk + 4][mr + 8];
            }
            unsigned bfg[8][2];
#pragma unroll
            for (int nt = 0; nt < 8; nt++) {
                int nc = wn + nt * 8 + qr;
                bfg[nt][0] = Bs[cur][qk    ][nc];
                bfg[nt][1] = Bs[cur][qk + 4][nc];
            }
#pragma unroll
            for (int mt = 0; mt < 2; mt++)
#pragma unroll
                for (int nt = 0; nt < 8; nt++)
                    MMA_F16(acc[mt][nt], af[mt], bfg[nt]);
        }

        if (more) {
            int nxt = cur ^ 1;
            As[nxt][ka2 + 0][ma] = pack_h2(a0.x, a0.y);
            As[nxt][ka2 + 1][ma] = pack_h2(a0.z, a0.w);
            As[nxt][ka2 + 2][ma] = pack_h2(a1.x, a1.y);
            As[nxt][ka2 + 3][ma] = pack_h2(a1.z, a1.w);
            *(uint4*)&Bs[nxt][kp][nb] = make_uint4(pack_h2(b0.x, b1.x), pack_h2(b0.y, b1.y),
                                                   pack_h2(b0.z, b1.z), pack_h2(b0.w, b1.w));
        }
        __syncthreads();
    }

    // ---------------- epilogue ----------------
    float* C = p.C + z * p.sCz;
    const float* bias = p.bias ? (p.bias + z * p.sbz) : nullptr;
    const int*   crow = p.crow ? (p.crow + z * p.sCrz) : nullptr;
    const float* rsc  = p.rsc  ? (p.rsc  + z * p.sRz)  : nullptr;

#pragma unroll
    for (int mt = 0; mt < 2; mt++) {
#pragma unroll
        for (int half = 0; half < 2; half++) {
            int r = m0 + wm + mt * 16 + qr + half * 8;
            if (r >= Mz) continue;
            long cr = crow ? (long)crow[r] : (long)r;
            float sc = rsc ? rsc[r] : 1.0f;
            float* crp = C + cr * p.ldc;
#pragma unroll
            for (int nt = 0; nt < 8; nt++) {
                int c = n0 + wn + nt * 8 + qk * 2;
                float v0 = acc[mt][nt][half * 2 + 0];
                float v1 = acc[mt][nt][half * 2 + 1];
                if (bias) { v0 += bias[c]; v1 += bias[c + 1]; }
                if (p.epi == 2) {
                    v0 = 0.5f * v0 * (1.0f + erff(v0 * 0.70710678118654752f));
                    v1 = 0.5f * v1 * (1.0f + erff(v1 * 0.70710678118654752f));
                }
                float* cp = crp + c;
                if (p.epi == 1) {
                    float2 old = *(float2*)cp;
                    *(float2*)cp = make_float2(old.x + v0, old.y + v1);
                } else {
                    *(float2*)cp = make_float2(v0 * sc, v1 * sc);
                }
            }
        }
    }
}

// ---------------- patchify ----------------
__global__ void patchify_kernel(const float* __restrict__ x, float* __restrict__ P)
{
    int row = blockIdx.x;              // b*196 + pidx
    int b = row / NP, pidx = row % NP;
    int gy = pidx / 14, gx = pidx % 14;
    for (int k = threadIdx.x; k < Dm; k += 256) {
        int c = k >> 8, rem = k & 255, py = rem >> 4, px = rem & 15;
        P[(long)row * Dm + k] =
            x[((long)(b * 3 + c) * 224 + gy * 16 + py) * 224 + gx * 16 + px];
    }
}

// ---------------- assemble tokens (cls + pos) ----------------
__global__ void assemble_kernel(const float* __restrict__ tok, const float* __restrict__ cls,
                                const float* __restrict__ pos, float* __restrict__ h)
{
    int t = blockIdx.x;
    int b = t / Nt, n = t % Nt;
    for (int c = threadIdx.x; c < Dm; c += 256) {
        float v = (n == 0) ? cls[c] : tok[(long)(b * NP + n - 1) * Dm + c];
        h[(long)t * Dm + c] = v + pos[(long)n * Dm + c];
    }
}

// ---------------- layernorm (768 wide, 256 threads) ----------------
__global__ void ln_kernel(const float* __restrict__ x, const float* __restrict__ g,
                          const float* __restrict__ bb, float* __restrict__ y, int row_mul)
{
    int ro = blockIdx.x;
    const float* xr = x + (long)ro * row_mul * Dm;
    float* yr = y + (long)ro * Dm;
    int tid = threadIdx.x;
    float v0 = xr[tid], v1 = xr[tid + 256], v2 = xr[tid + 512];
    float s  = v0 + v1 + v2;
    float ss = v0 * v0 + v1 * v1 + v2 * v2;
#pragma unroll
    for (int off = 16; off; off >>= 1) {
        s  += __shfl_xor_sync(0xffffffffu, s,  off);
        ss += __shfl_xor_sync(0xffffffffu, ss, off);
    }
    __shared__ float sh[16];
    __shared__ float stat[2];
    int w = tid >> 5, l = tid & 31;
    if (l == 0) { sh[w] = s; sh[8 + w] = ss; }
    __syncthreads();
    if (tid == 0) {
        float S = 0.f, SS = 0.f;
        for (int i = 0; i < 8; i++) { S += sh[i]; SS += sh[8 + i]; }
        float m = S * (1.0f / 768.0f);
        float var = SS * (1.0f / 768.0f) - m * m;
        stat[0] = m;
        stat[1] = rsqrtf(var + 1e-5f);
    }
    __syncthreads();
    float m = stat[0], r = stat[1];
    yr[tid]       = (v0 - m) * r * g[tid]       + bb[tid];
    yr[tid + 256] = (v1 - m) * r * g[tid + 256] + bb[tid + 256];
    yr[tid + 512] = (v2 - m) * r * g[tid + 512] + bb[tid + 512];
}

// ---------------- attention (per (head, batch) block) ----------------
static constexpr int ATT_SMEM = (2 * Nt * HD + 8 * 208) * 4;   // ~107.5 KB

__global__ void attn_kernel(const float* __restrict__ qkv, float* __restrict__ out)
{
    extern __shared__ float sm[];
    float* Ks = sm;
    float* Vs = sm + Nt * HD;
    float* Ps = sm + 2 * Nt * HD;

    int h = blockIdx.x, b = blockIdx.y;
    int tid = threadIdx.x;

    for (int idx = tid; idx < Nt * 16; idx += 256) {
        int n = idx >> 4, d4 = (idx & 15) << 2;
        const float* base = qkv + (long)(b * Nt + n) * (3 * Dm) + h * HD + d4;
        *(float4*)&Ks[n * HD + d4] = *(const float4*)(base + Dm);
        *(float4*)&Vs[n * HD + d4] = *(const float4*)(base + 2 * Dm);
    }
    __syncthreads();

    int warp = tid >> 5, lane = tid & 31;
    float* pr = Ps + warp * 208;

    for (int r = warp; r < Nt; r += 8) {
        const float* qg = qkv + (long)(b * Nt + r) * (3 * Dm) + h * HD;
        float q[HD];
#pragma unroll
        for (int d4 = 0; d4 < HD; d4 += 4)
            *(float4*)&q[d4] = *(const float4*)(qg + d4);

        float mx = -1e30f;
        for (int j = lane; j < Nt; j += 32) {
            const float* kr = Ks + j * HD;
            float sv = 0.f;
#pragma unroll
            for (int d4 = 0; d4 < HD; d4 += 4) {
                float4 k4 = *(const float4*)(kr + d4);
                sv += q[d4] * k4.x + q[d4 + 1] * k4.y + q[d4 + 2] * k4.z + q[d4 + 3] * k4.w;
            }
            sv *= 0.125f;
            pr[j] = sv;
            mx = fmaxf(mx, sv);
        }
#pragma unroll
        for (int off = 16; off; off >>= 1)
            mx = fmaxf(mx, __shfl_xor_sync(0xffffffffu, mx, off));

        __syncwarp();
        float sum = 0.f;
        for (int j = lane; j < Nt; j += 32) {
            float pv = expf(pr[j] - mx);
            pr[j] = pv;
            sum += pv;
        }
#pragma unroll
        for (int off = 16; off; off >>= 1)
            sum += __shfl_xor_sync(0xffffffffu, sum, off);
        __syncwarp();

        float inv = 1.0f / sum;
        float o0 = 0.f, o1 = 0.f;
        for (int j = 0; j < Nt; j++) {
            float pv = pr[j];
            o0 += pv * Vs[j * HD + lane];
            o1 += pv * Vs[j * HD + lane + 32];
        }
        float* op = out + (long)(b * Nt + r) * Dm + h * HD;
        op[lane]      = o0 * inv;
        op[lane + 32] = o1 * inv;
        __syncwarp();
    }
}

// ---------------- MoE gate + routing ----------------
__global__ void zero_cnt_kernel(int* c) { if (threadIdx.x < 8) c[threadIdx.x] = 0; }

__global__ void gate_kernel(const float* __restrict__ y, const float* __restrict__ wg,
                            int* cnt, int* list, int* crow, float* scale)
{
    int warp = threadIdx.x >> 5, lane = threadIdx.x & 31;
    int t = blockIdx.x * 8 + warp;
    if (t >= (int)Tt) return;
    float lg[8] = {0, 0, 0, 0, 0, 0, 0, 0};
    const float* yr = y + (long)t * Dm;
    for (int d = lane; d < Dm; d += 32) {
        float xv = yr[d];
        const float* w = wg + d * Em;
#pragma unroll
        for (int e = 0; e < 8; e++) lg[e] += xv * w[e];
    }
#pragma unroll
    for (int e = 0; e < 8; e++)
#pragma unroll
        for (int off = 16; off; off >>= 1)
            lg[e] += __shfl_xor_sync(0xffffffffu, lg[e], off);
    if (lane == 0) {
        int e0 = 0; float v0 = lg[0];
        for (int e = 1; e < 8; e++) if (lg[e] > v0) { v0 = lg[e]; e0 = e; }
        int e1 = (e0 == 0) ? 1 : 0; float v1 = lg[e1];
        for (int e = 0; e < 8; e++)
            if (e != e0 && lg[e] > v1) { v1 = lg[e]; e1 = e; }
        float p0 = 1.0f / (1.0f + expf(v1 - v0));
        float p1 = 1.0f - p0;
        int pos = atomicAdd(&cnt[e0], 1);
        list[e0 * 1576 + pos] = t; crow[e0 * 1576 + pos] = t * 2;     scale[e0 * 1576 + pos] = p0;
        pos = atomicAdd(&cnt[e1], 1);
        list[e1 * 1576 + pos] = t; crow[e1 * 1576 + pos] = t * 2 + 1; scale[e1 * 1576 + pos] = p1;
    }
}

__global__ void moe_combine_kernel(const float* __restrict__ mo, float* __restrict__ h)
{
    long t = blockIdx.x;
    for (int c = threadIdx.x; c < Dm; c += 256)
        h[t * Dm + c] += mo[t * 2 * Dm + c] + mo[t * 2 * Dm + Dm + c];
}

// ---------------- head ----------------
__global__ void head_kernel(const float* __restrict__ cls, const float* __restrict__ w,
                            const float* __restrict__ bh, float* __restrict__ out)
{
    int c = blockIdx.x * 256 + threadIdx.x;
    int b = blockIdx.y;
    if (c >= 1000) return;
    const float* cr = cls + (long)b * Dm;
    float s0 = 0.f, s1 = 0.f, s2 = 0.f, s3 = 0.f;
    for (int d = 0; d < Dm; d += 4) {
        s0 += cr[d]     * w[(long)d * 1000 + c];
        s1 += cr[d + 1] * w[(long)(d + 1) * 1000 + c];
        s2 += cr[d + 2] * w[(long)(d + 2) * 1000 + c];
        s3 += cr[d + 3] * w[(long)(d + 3) * 1000 + c];
    }
    out[(long)b * 1000 + c] = (s0 + s1) + (s2 + s3) + bh[c];
}

// ---------------- host-side launcher ----------------
static inline void launch_gemm(const float* A, long sAz, int lda,
                               const float* B, long sBz, int ldb,
                               const float* bias, long sbz,
                               float* C, long sCz, int ldc,
                               int M, const int* cnt, int N, int K,
                               const int* arow, long sArz,
                               const int* crow, long sCrz,
                               const float* rsc, long sRz,
                               int epi, int Z)
{
    GemmP p;
    p.A = A; p.B = B; p.bias = bias; p.C = C;
    p.lda = lda; p.ldb = ldb; p.ldc = ldc;
    p.M = M; p.N = N; p.K = K;
    p.sAz = sAz; p.sBz = sBz; p.sbz = sbz; p.sCz = sCz;
    p.cnt = cnt;
    p.arow = arow; p.sArz = sArz;
    p.crow = crow; p.sCrz = sCrz;
    p.rsc = rsc;  p.sRz  = sRz;
    p.epi = epi;
    dim3 grid(N / 128, (M + 127) / 128, Z);
    gemm_f16<<<grid, 256>>>(p);
}

extern "C" void kernel_launch(void* const* d_in, const int* in_sizes, int n_in,
                              void* d_out, int out_size)
{
    const float* X      = (const float*)d_in[0];
    const float* Wpatch = (const float*)d_in[1];
    const float* Bpatch = (const float*)d_in[2];
    const float* Cls    = (const float*)d_in[3];
    const float* Pos    = (const float*)d_in[4];
    const float* Ln1g   = (const float*)d_in[5];
    const float* Ln1b   = (const float*)d_in[6];
    const float* Wqkv   = (const float*)d_in[7];
    const float* Wproj  = (const float*)d_in[8];
    const float* Bproj  = (const float*)d_in[9];
    const float* Ln2g   = (const float*)d_in[10];
    const float* Ln2b   = (const float*)d_in[11];
    const float* Wfc1   = (const float*)d_in[12];
    const float* Bfc1   = (const float*)d_in[13];
    const float* Wfc2   = (const float*)d_in[14];
    const float* Bfc2   = (const float*)d_in[15];
    const float* Wgate  = (const float*)d_in[16];
    const float* We1    = (const float*)d_in[17];
    const float* Be1    = (const float*)d_in[18];
    const float* We2    = (const float*)d_in[19];
    const float* Be2    = (const float*)d_in[20];
    const float* Lnfg   = (const float*)d_in[21];
    const float* Lnfb   = (const float*)d_in[22];
    const float* Whead  = (const float*)d_in[23];
    const float* Bhead  = (const float*)d_in[24];
    float* OUT = (float*)d_out;

    float* FB = nullptr; int* IB = nullptr;
    cudaGetSymbolAddress((void**)&FB, g_fbuf);
    cudaGetSymbolAddress((void**)&IB, g_ibuf);

    float* H    = FB + OFF_H;
    float* Y    = FB + OFF_Y;
    float* QKV  = FB + OFF_QKV;
    float* AT   = FB + OFF_ATTN;
    float* HID  = FB + OFF_HID;
    float* MO   = FB + OFF_MOE;
    float* CLSB = FB + OFF_CLS;
    float* PB   = FB + OFF_PATCH;
    float* SCB  = FB + OFF_SCALE;
    int* CNT  = IB;
    int* LIST = IB + 8;
    int* CROW = IB + 8 + 8 * 1576;

    cudaFuncSetAttribute(attn_kernel, cudaFuncAttributeMaxDynamicSharedMemorySize, ATT_SMEM);

    const int T = (int)Tt;

    // patch embed
    patchify_kernel<<<Bb * NP, 256>>>(X, PB);
    launch_gemm(PB, 0, Dm, Wpatch, 0, Dm, Bpatch, 0,
                AT, 0, Dm, Bb * NP, nullptr, Dm, Dm,
                nullptr, 0, nullptr, 0, nullptr, 0, /*epi*/0, 1);
    assemble_kernel<<<T, 256>>>(AT, Cls, Pos, H);

    for (int i = 0; i < 4; i++) {
        // attention block
        ln_kernel<<<T, 256>>>(H, Ln1g + i * Dm, Ln1b + i * Dm, Y, 1);
        launch_gemm(Y, 0, Dm, Wqkv + (long)i * Dm * 3 * Dm, 0, 3 * Dm, nullptr, 0,
                    QKV, 0, 3 * Dm, T, nullptr, 3 * Dm, Dm,
                    nullptr, 0, nullptr, 0, nullptr, 0, 0, 1);
        attn_kernel<<<dim3(NHd, Bb), 256, ATT_SMEM>>>(QKV, AT);
        launch_gemm(AT, 0, Dm, Wproj + (long)i * Dm * Dm, 0, Dm, Bproj + (long)i * Dm, 0,
                    H, 0, Dm, T, nullptr, Dm, Dm,
                    nullptr, 0, nullptr, 0, nullptr, 0, /*+=*/1, 1);

        // MLP block
        ln_kernel<<<T, 256>>>(H, Ln2g + i * Dm, Ln2b + i * Dm, Y, 1);
        int j = i >> 1;
        if ((i & 1) == 0) {
            launch_gemm(Y, 0, Dm, Wfc1 + (long)j * Dm * HIDm, 0, HIDm,
                        Bfc1 + (long)j * HIDm, 0,
                        HID, 0, HIDm, T, nullptr, HIDm, Dm,
                        nullptr, 0, nullptr, 0, nullptr, 0, /*gelu*/2, 1);
            launch_gemm(HID, 0, HIDm, Wfc2 + (long)j * HIDm * Dm, 0, Dm,
                        Bfc2 + (long)j * Dm, 0,
                        H, 0, Dm, T, nullptr, Dm, HIDm,
                        nullptr, 0, nullptr, 0, nullptr, 0, /*+=*/1, 1);
        } else {
            zero_cnt_kernel<<<1, 8>>>(CNT);
            gate_kernel<<<(T + 7) / 8, 256>>>(Y, Wgate + (long)j * Dm * Em,
                                              CNT, LIST, CROW, SCB);
            // expert fc1 (gathered rows of Y) -> gelu -> HID[e]
            launch_gemm(Y, 0, Dm,
                        We1 + (long)j * Em * Dm * HIDm, (long)Dm * HIDm, HIDm,
                        Be1 + (long)j * Em * HIDm, HIDm,
                        HID, (long)T * HIDm, HIDm,
                        T, CNT, HIDm, Dm,
                        LIST, 1576, nullptr, 0, nullptr, 0, /*gelu*/2, Em);
            // expert fc2 -> scaled scatter into (token, slot) rows of MO
            launch_gemm(HID, (long)T * HIDm, HIDm,
                        We2 + (long)j * Em * HIDm * Dm, (long)HIDm * Dm, Dm,
                        Be2 + (long)j * Em * Dm, Dm,
                        MO, 0, Dm,
                        T, CNT, Dm, HIDm,
                        nullptr, 0, CROW, 1576, SCB, 1576, /*scatter*/3, Em);
            moe_combine_kernel<<<T, 256>>>(MO, H);
        }
    }

    // final LN on cls rows + head
    ln_kernel<<<Bb, 256>>>(H, Lnfg, Lnfb, CLSB, Nt);
    head_kernel<<<dim3(4, Bb), 256>>>(CLSB, Whead, Bhead, OUT);
}